// round 8
// baseline (speedup 1.0000x reference)
#include <cuda_runtime.h>
#include <cuda_bf16.h>
#include <cstdint>
#include <math.h>

// ---------------------------------------------------------------------------
// Problem constants
// ---------------------------------------------------------------------------
#define BATCH 4
#define NH 16
#define LQ 2048
#define LK 2048
#define DHEAD 64

#define GM 8192            // B*LQ
#define GN 1024            // H*DHEAD
#define GK 1024            // D_MODEL

#define SCALE_L2E 0.1803368801111204f   // (1/8) * log2(e)
#define MASKNEG  -1.442695040e9f        // -1e9 * log2(e)

#define KT 64              // key tile

// Scratch: projected q/k/v as bf16 hi/lo, layout [B, S, H, D]
__device__ __nv_bfloat16 g_qhi[GM * GN];
__device__ __nv_bfloat16 g_qlo[GM * GN];
__device__ __nv_bfloat16 g_khi[GM * GN];
__device__ __nv_bfloat16 g_klo[GM * GN];
__device__ __nv_bfloat16 g_vhi[GM * GN];
__device__ __nv_bfloat16 g_vlo[GM * GN];
__device__ __nv_bfloat16 g_ahi[GM * GK];
__device__ __nv_bfloat16 g_alo[GM * GK];
__device__ __nv_bfloat16 g_whi[GN * GK];   // transposed: [n][k]
__device__ __nv_bfloat16 g_wlo[GN * GK];

// Key compaction: valid-key indices per batch + compact head-major k/v
__device__ int g_idx[BATCH * LK];
__device__ int g_nv[BATCH];
__device__ int g_nvt[BATCH];
__device__ __nv_bfloat16 g_ckh[BATCH * NH * LK * DHEAD];
__device__ __nv_bfloat16 g_ckl[BATCH * NH * LK * DHEAD];
__device__ __nv_bfloat16 g_cvh[BATCH * NH * LK * DHEAD];
__device__ __nv_bfloat16 g_cvl[BATCH * NH * LK * DHEAD];

// ---------------------------------------------------------------------------
// Helpers (baseline PTX: ldmatrix / mma.sync / cp.async)
// ---------------------------------------------------------------------------
__device__ __forceinline__ uint32_t smem_u32(const void* p) {
    uint32_t a;
    asm("{ .reg .u64 t; cvta.to.shared.u64 t, %1; cvt.u32.u64 %0, t; }"
        : "=r"(a) : "l"(p));
    return a;
}
__device__ __forceinline__ void cp_async16(uint32_t s, const void* g) {
    asm volatile("cp.async.cg.shared.global [%0], [%1], 16;" :: "r"(s), "l"(g));
}
#define CP_COMMIT() asm volatile("cp.async.commit_group;")
#define CP_WAIT(n) asm volatile("cp.async.wait_group %0;" :: "n"(n))

__device__ __forceinline__ void ldsm_x4(uint32_t* r, uint32_t addr) {
    asm volatile("ldmatrix.sync.aligned.m8n8.x4.shared.b16 {%0,%1,%2,%3}, [%4];"
                 : "=r"(r[0]), "=r"(r[1]), "=r"(r[2]), "=r"(r[3]) : "r"(addr));
}
__device__ __forceinline__ void ldsm_x2(uint32_t* r, uint32_t addr) {
    asm volatile("ldmatrix.sync.aligned.m8n8.x2.shared.b16 {%0,%1}, [%2];"
                 : "=r"(r[0]), "=r"(r[1]) : "r"(addr));
}
__device__ __forceinline__ void ldsm_x4t(uint32_t* r, uint32_t addr) {
    asm volatile("ldmatrix.sync.aligned.m8n8.x4.trans.shared.b16 {%0,%1,%2,%3}, [%4];"
                 : "=r"(r[0]), "=r"(r[1]), "=r"(r[2]), "=r"(r[3]) : "r"(addr));
}
__device__ __forceinline__ void mma16816(float* c, const uint32_t* a, const uint32_t* b) {
    asm volatile(
        "mma.sync.aligned.m16n8k16.row.col.f32.bf16.bf16.f32 "
        "{%0,%1,%2,%3}, {%4,%5,%6,%7}, {%8,%9}, {%0,%1,%2,%3};"
        : "+f"(c[0]), "+f"(c[1]), "+f"(c[2]), "+f"(c[3])
        : "r"(a[0]), "r"(a[1]), "r"(a[2]), "r"(a[3]), "r"(b[0]), "r"(b[1]));
}

// (x,y) -> packed bf16x2 hi and lo residual
__device__ __forceinline__ void split2(float x, float y, uint32_t& h, uint32_t& l) {
    __nv_bfloat162 hh = __floats2bfloat162_rn(x, y);
    float hx = __bfloat162float(hh.x), hy = __bfloat162float(hh.y);
    __nv_bfloat162 ll = __floats2bfloat162_rn(x - hx, y - hy);
    h = *(uint32_t*)&hh;
    l = *(uint32_t*)&ll;
}

// ---------------------------------------------------------------------------
// Input conversion kernels
// ---------------------------------------------------------------------------
__device__ __forceinline__ uint32_t pack2(float a, float b) {
    __nv_bfloat162 t = __floats2bfloat162_rn(a, b);
    return *(uint32_t*)&t;
}

__global__ __launch_bounds__(256) void split_kernel(const float* __restrict__ x,
                                                    uint2* __restrict__ hi,
                                                    uint2* __restrict__ lo, int n4) {
    int i = blockIdx.x * 256 + threadIdx.x;
    if (i >= n4) return;
    float4 v = ((const float4*)x)[i];
    float h0 = __bfloat162float(__float2bfloat16(v.x));
    float h1 = __bfloat162float(__float2bfloat16(v.y));
    float h2 = __bfloat162float(__float2bfloat16(v.z));
    float h3 = __bfloat162float(__float2bfloat16(v.w));
    uint2 H, L;
    H.x = pack2(h0, h1);
    H.y = pack2(h2, h3);
    L.x = pack2(v.x - h0, v.y - h1);
    L.y = pack2(v.z - h2, v.w - h3);
    hi[i] = H;
    lo[i] = L;
}

__global__ __launch_bounds__(256) void wtrans_kernel(const float* __restrict__ W,
                                                     __nv_bfloat16* __restrict__ thi,
                                                     __nv_bfloat16* __restrict__ tlo) {
    __shared__ float t[32][33];
    int n0 = blockIdx.x * 32, k0 = blockIdx.y * 32;
    int tx = threadIdx.x & 31, ty0 = threadIdx.x >> 5;
#pragma unroll
    for (int i = 0; i < 4; i++) {
        int ty = ty0 + i * 8;
        t[ty][tx] = W[(size_t)(k0 + ty) * GN + n0 + tx];
    }
    __syncthreads();
#pragma unroll
    for (int i = 0; i < 4; i++) {
        int ty = ty0 + i * 8;
        float v = t[tx][ty];
        __nv_bfloat16 h = __float2bfloat16(v);
        size_t o = (size_t)(n0 + ty) * GK + k0 + tx;
        thi[o] = h;
        tlo[o] = __float2bfloat16(v - __bfloat162float(h));
    }
}

// ---------------------------------------------------------------------------
// Mask scan: per-batch valid-key index list (block-wide scan, 1 CTA/batch)
// ---------------------------------------------------------------------------
__global__ __launch_bounds__(256) void mask_scan(const int* __restrict__ mask) {
    __shared__ int wsum[8];
    const int b = blockIdx.x;
    const int* m = mask + b * LK;
    const int tid = threadIdx.x;
    const int lane = tid & 31, w = tid >> 5;

    int v[8], s = 0;
#pragma unroll
    for (int i = 0; i < 8; i++) {
        v[i] = (m[tid * 8 + i] != 0);
        s += v[i];
    }
    // warp inclusive scan of s
    int ps = s;
#pragma unroll
    for (int o = 1; o < 32; o <<= 1) {
        int t = __shfl_up_sync(0xffffffffu, ps, o);
        if (lane >= o) ps += t;
    }
    if (lane == 31) wsum[w] = ps;
    __syncthreads();
    if (w == 0) {
        int t = (lane < 8) ? wsum[lane] : 0;
#pragma unroll
        for (int o = 1; o < 8; o <<= 1) {
            int u = __shfl_up_sync(0xffffffffu, t, o);
            if (lane >= o) t += u;
        }
        if (lane < 8) wsum[lane] = t;
    }
    __syncthreads();
    int excl = ps - s + (w ? wsum[w - 1] : 0);
#pragma unroll
    for (int i = 0; i < 8; i++) {
        if (v[i]) g_idx[b * LK + excl++] = tid * 8 + i;
    }
    if (tid == 255) {
        int nv = wsum[7];
        g_nv[b] = nv;
        g_nvt[b] = (nv + KT - 1) / KT;
    }
}

// ---------------------------------------------------------------------------
// Gather valid keys into compact head-major buffers [B][H][j][D].
// Pad rows (j in [nv, nvt*KT)) are zero-filled.
// ---------------------------------------------------------------------------
__global__ __launch_bounds__(256) void gather_kv() {
    const int jt = blockIdx.x;      // 64-key tile
    const int h = blockIdx.y;
    const int b = blockIdx.z;
    if (jt >= g_nvt[b]) return;
    const int nv = g_nv[b];
    const int tid = threadIdx.x;

    const size_t dst_base = ((size_t)(b * NH + h)) * LK;
    const uint4 zero = make_uint4(0, 0, 0, 0);
#pragma unroll
    for (int i = 0; i < 8; i++) {
        int t = tid + i * 256;      // 0..2047
        int arr = t >> 9;           // which of 4 arrays
        int r = (t >> 3) & 63;      // row within tile
        int c8 = (t & 7) * 8;       // elem col
        int j = jt * KT + r;
        uint4 val = zero;
        if (j < nv) {
            int s = g_idx[b * LK + j];
            size_t so = (((size_t)b * LK + s) * NH + h) * DHEAD + c8;
            const __nv_bfloat16* src = (arr == 0) ? g_khi
                                     : (arr == 1) ? g_klo
                                     : (arr == 2) ? g_vhi : g_vlo;
            val = *(const uint4*)(src + so);
        }
        __nv_bfloat16* dst = (arr == 0) ? g_ckh
                           : (arr == 1) ? g_ckl
                           : (arr == 2) ? g_cvh : g_cvl;
        *(uint4*)(dst + (dst_base + j) * DHEAD + c8) = val;
    }
}

// ---------------------------------------------------------------------------
// Projection GEMM (mma.sync, bf16 hi/lo 3-term). Writes bf16 hi/lo outputs.
// ---------------------------------------------------------------------------
#define PBM 128
#define PBN 128
#define PBK 32
#define PPITCH 40
#define PTILE_B (128 * PPITCH * 2)
#define POFF_AHI 0
#define POFF_ALO (POFF_AHI + PTILE_B)
#define POFF_BHI (POFF_ALO + PTILE_B)
#define POFF_BLO (POFF_BHI + PTILE_B)
#define PSTAGE_B (4 * PTILE_B)
#define PSMEM_B (2 * PSTAGE_B)
#define PNCHUNK (GK / PBK)

__global__ __launch_bounds__(256) void proj_mma(const __nv_bfloat16* __restrict__ Ahi,
                                                const __nv_bfloat16* __restrict__ Alo,
                                                const __nv_bfloat16* __restrict__ Bhi,
                                                const __nv_bfloat16* __restrict__ Blo,
                                                const float* __restrict__ bias,
                                                __nv_bfloat16* __restrict__ Chi,
                                                __nv_bfloat16* __restrict__ Clo) {
    extern __shared__ char smem[];
    const uint32_t sb = smem_u32(smem);
    const int tid = threadIdx.x;
    const int lane = tid & 31;
    const int warp = tid >> 5;
    const int wm = warp & 1;
    const int wn = warp >> 1;
    const int rowBase = blockIdx.y * PBM;
    const int colBase = blockIdx.x * PBN;

    float acc[4][4][4];
#pragma unroll
    for (int i = 0; i < 4; i++)
#pragma unroll
        for (int j = 0; j < 4; j++)
#pragma unroll
            for (int r = 0; r < 4; r++) acc[i][j][r] = 0.f;

    auto load_chunk = [&](int stage, int kb) {
        uint32_t s0 = sb + stage * PSTAGE_B;
#pragma unroll
        for (int i = 0; i < 2; i++) {
            int c = tid + i * 256;
            int r = c >> 2;
            int col = (c & 3) * 8;
            uint32_t so = (uint32_t)(r * (PPITCH * 2) + col * 2);
            size_t ga = (size_t)(rowBase + r) * GK + kb + col;
            size_t gb = (size_t)(colBase + r) * GK + kb + col;
            cp_async16(s0 + POFF_AHI + so, Ahi + ga);
            cp_async16(s0 + POFF_ALO + so, Alo + ga);
            cp_async16(s0 + POFF_BHI + so, Bhi + gb);
            cp_async16(s0 + POFF_BLO + so, Blo + gb);
        }
    };

    const int lr = lane & 7;
    const int lgA_m = ((lane >> 3) & 1) * 8;
    const int lgA_k = (lane >> 4) * 8;
    const int lgB_k = ((lane >> 3) & 1) * 8;

    load_chunk(0, 0);
    CP_COMMIT();

    for (int ch = 0; ch < PNCHUNK; ch++) {
        if (ch + 1 < PNCHUNK) {
            load_chunk((ch + 1) & 1, (ch + 1) * PBK);
            CP_COMMIT();
            CP_WAIT(1);
        } else {
            CP_WAIT(0);
        }
        __syncthreads();

        const uint32_t s0 = sb + (ch & 1) * PSTAGE_B;
        const uint32_t aHi = s0 + POFF_AHI, aLo = s0 + POFF_ALO;
        const uint32_t bHi = s0 + POFF_BHI, bLo = s0 + POFF_BLO;

#pragma unroll
        for (int ks = 0; ks < PBK; ks += 16) {
            uint32_t ahi[4][4], alo[4][4];
#pragma unroll
            for (int mt = 0; mt < 4; mt++) {
                int row = wm * 64 + mt * 16 + lgA_m + lr;
                uint32_t off = (uint32_t)(row * (PPITCH * 2) + (ks + lgA_k) * 2);
                ldsm_x4(ahi[mt], aHi + off);
                ldsm_x4(alo[mt], aLo + off);
            }
#pragma unroll
            for (int nt = 0; nt < 4; nt++) {
                int brow = wn * 32 + nt * 8 + lr;
                uint32_t off = (uint32_t)(brow * (PPITCH * 2) + (ks + lgB_k) * 2);
                uint32_t bh[2], bl[2];
                ldsm_x2(bh, bHi + off);
                ldsm_x2(bl, bLo + off);
#pragma unroll
                for (int mt = 0; mt < 4; mt++) {
                    mma16816(acc[mt][nt], ahi[mt], bh);
                    mma16816(acc[mt][nt], ahi[mt], bl);
                    mma16816(acc[mt][nt], alo[mt], bh);
                }
            }
        }
        __syncthreads();
    }

    // Epilogue: bias add, then split to bf16 hi/lo and store
#pragma unroll
    for (int mt = 0; mt < 4; mt++) {
#pragma unroll
        for (int nt = 0; nt < 4; nt++) {
            int row = rowBase + wm * 64 + mt * 16 + (lane >> 2);
            int col = colBase + wn * 32 + nt * 8 + (lane & 3) * 2;
            float2 bb = *(const float2*)&bias[col];
            float v0 = acc[mt][nt][0] + bb.x, v1 = acc[mt][nt][1] + bb.y;
            float v2 = acc[mt][nt][2] + bb.x, v3 = acc[mt][nt][3] + bb.y;
            uint32_t h, l;
            split2(v0, v1, h, l);
            *(uint32_t*)(Chi + (size_t)row * GN + col) = h;
            *(uint32_t*)(Clo + (size_t)row * GN + col) = l;
            split2(v2, v3, h, l);
            *(uint32_t*)(Chi + (size_t)(row + 8) * GN + col) = h;
            *(uint32_t*)(Clo + (size_t)(row + 8) * GN + col) = l;
        }
    }
}

// ---------------------------------------------------------------------------
// Flash attention on mma.sync with compacted keys.
// CTA: 128 queries x (b,h). 8 warps x 16 query rows. Dynamic tile count.
// ---------------------------------------------------------------------------
#define AQ 128
#define APITCH 72                       // bf16 elems per smem row (144 B)
#define AT_QH 0
#define AT_QL (AT_QH + AQ * APITCH * 2)             // 18432
#define AT_ST (AT_QL + AQ * APITCH * 2)             // 36864
#define AT_ARR (KT * APITCH * 2)                    // 9216
#define AT_STG (4 * AT_ARR)                         // 36864
#define AT_SMEM (AT_ST + 2 * AT_STG)                // 110592

__global__ __launch_bounds__(256) void attn_mma(float* __restrict__ out) {
    extern __shared__ char smem[];
    const uint32_t sb = smem_u32(smem);

    const int tid = threadIdx.x;
    const int lane = tid & 31;
    const int w = tid >> 5;
    const int q0 = blockIdx.x * AQ;
    const int h = blockIdx.y;
    const int b = blockIdx.z;

    const int nv = g_nv[b];
    const int nt = g_nvt[b];

    const int lr = lane & 7;
    const int lgA_m = ((lane >> 3) & 1) * 8;
    const int lgA_k = (lane >> 4) * 8;
    const int lgBm = ((lane >> 4) & 1) * 8;     // B x4: row select
    const int lgBk = ((lane >> 3) & 1) * 8;     // B x4: col select
    const int qr = lane >> 2;
    const int qc = (lane & 3) * 2;

    // ---- prologue loads: q tile + kv tile 0 (and 1) ----
    const size_t hoff = (size_t)h * DHEAD;
#pragma unroll
    for (int i = 0; i < 8; i++) {
        int seg = tid + i * 256;
        int arr = seg >> 10;
        int s2 = seg & 1023;
        int row = s2 >> 3, c8 = (s2 & 7) * 8;
        const __nv_bfloat16* g = (arr ? g_qlo : g_qhi) +
            (((size_t)b * LQ + q0 + row) * NH) * DHEAD + hoff + c8;
        cp_async16(sb + (arr ? AT_QL : AT_QH) + (uint32_t)((row * APITCH + c8) * 2), g);
    }

    const size_t cb = (size_t)(b * NH + h) * LK;
    auto load_kv = [&](int stage, int kt) {
        uint32_t s0 = sb + AT_ST + stage * AT_STG;
#pragma unroll
        for (int i = 0; i < 2; i++) {
            int seg = tid + i * 256;
            int row = seg >> 3, c8 = (seg & 7) * 8;
            size_t go = (cb + kt + row) * DHEAD + c8;
            uint32_t so = (uint32_t)((row * APITCH + c8) * 2);
            cp_async16(s0 + 0 * AT_ARR + so, g_ckh + go);
            cp_async16(s0 + 1 * AT_ARR + so, g_ckl + go);
            cp_async16(s0 + 2 * AT_ARR + so, g_cvh + go);
            cp_async16(s0 + 3 * AT_ARR + so, g_cvl + go);
        }
    };
    load_kv(0, 0);
    CP_COMMIT();
    if (nt > 1) {
        load_kv(1, KT);
        CP_COMMIT();
        CP_WAIT(1);
    } else {
        CP_WAIT(0);
    }
    __syncthreads();

    // ---- q fragments to registers ----
    uint32_t qh[4][4], ql[4][4];
#pragma unroll
    for (int ks = 0; ks < 4; ks++) {
        uint32_t off = (uint32_t)(((w * 16 + lgA_m + lr) * APITCH + ks * 16 + lgA_k) * 2);
        ldsm_x4(qh[ks], sb + AT_QH + off);
        ldsm_x4(ql[ks], sb + AT_QL + off);
    }

    float O[8][4];
#pragma unroll
    for (int d = 0; d < 8; d++) O[d][0] = O[d][1] = O[d][2] = O[d][3] = 0.f;
    float m0 = -INFINITY, m1 = -INFINITY, l0 = 0.f, l1 = 0.f;

    for (int it = 0; it < nt; it++) {
        const uint32_t s0 = sb + AT_ST + (it & 1) * AT_STG;
        const uint32_t kHi = s0, kLo = s0 + AT_ARR;
        const uint32_t vHi = s0 + 2 * AT_ARR, vLo = s0 + 3 * AT_ARR;
        const int ktb = it * KT;

        // ---- S = q . k^T (K fragments via ldmatrix.x4, paired n-blocks) ----
        float S[8][4];
#pragma unroll
        for (int nb = 0; nb < 8; nb++)
            S[nb][0] = S[nb][1] = S[nb][2] = S[nb][3] = 0.f;
#pragma unroll
        for (int ks = 0; ks < 4; ks++) {
#pragma unroll
            for (int nb2 = 0; nb2 < 4; nb2++) {
                uint32_t off =
                    (uint32_t)(((nb2 * 16 + lgBm + lr) * APITCH + ks * 16 + lgBk) * 2);
                uint32_t kh[4], kl[4];
                ldsm_x4(kh, kHi + off);
                ldsm_x4(kl, kLo + off);
                mma16816(S[2 * nb2], qh[ks], kh);
                mma16816(S[2 * nb2], qh[ks], kl);
                mma16816(S[2 * nb2], ql[ks], kh);
                mma16816(S[2 * nb2 + 1], qh[ks], kh + 2);
                mma16816(S[2 * nb2 + 1], qh[ks], kl + 2);
                mma16816(S[2 * nb2 + 1], ql[ks], kh + 2);
            }
        }

        // ---- scale + tail mask (register compare; exact) ----
#pragma unroll
        for (int nb = 0; nb < 8; nb++) {
            int p0 = ktb + nb * 8 + qc;
            bool v0 = p0 < nv, v1 = p0 + 1 < nv;
            S[nb][0] = v0 ? S[nb][0] * SCALE_L2E : MASKNEG;
            S[nb][1] = v1 ? S[nb][1] * SCALE_L2E : MASKNEG;
            S[nb][2] = v0 ? S[nb][2] * SCALE_L2E : MASKNEG;
            S[nb][3] = v1 ? S[nb][3] * SCALE_L2E : MASKNEG;
        }

        // ---- online softmax ----
        float tm0 = -INFINITY, tm1 = -INFINITY;
#pragma unroll
        for (int nb = 0; nb < 8; nb++) {
            tm0 = fmaxf(tm0, fmaxf(S[nb][0], S[nb][1]));
            tm1 = fmaxf(tm1, fmaxf(S[nb][2], S[nb][3]));
        }
        tm0 = fmaxf(tm0, __shfl_xor_sync(0xffffffffu, tm0, 1));
        tm0 = fmaxf(tm0, __shfl_xor_sync(0xffffffffu, tm0, 2));
        tm1 = fmaxf(tm1, __shfl_xor_sync(0xffffffffu, tm1, 1));
        tm1 = fmaxf(tm1, __shfl_xor_sync(0xffffffffu, tm1, 2));
        float m0n = fmaxf(m0, tm0), m1n = fmaxf(m1, tm1);
        float f0 = exp2f(m0 - m0n), f1 = exp2f(m1 - m1n);
        m0 = m0n;
        m1 = m1n;
#pragma unroll
        for (int d = 0; d < 8; d++) {
            O[d][0] *= f0;
            O[d][1] *= f0;
            O[d][2] *= f1;
            O[d][3] *= f1;
        }
        float rs0 = 0.f, rs1 = 0.f;
#pragma unroll
        for (int nb = 0; nb < 8; nb++) {
            S[nb][0] = exp2f(S[nb][0] - m0);
            S[nb][1] = exp2f(S[nb][1] - m0);
            S[nb][2] = exp2f(S[nb][2] - m1);
            S[nb][3] = exp2f(S[nb][3] - m1);
            rs0 += S[nb][0] + S[nb][1];
            rs1 += S[nb][2] + S[nb][3];
        }
        rs0 += __shfl_xor_sync(0xffffffffu, rs0, 1);
        rs0 += __shfl_xor_sync(0xffffffffu, rs0, 2);
        rs1 += __shfl_xor_sync(0xffffffffu, rs1, 1);
        rs1 += __shfl_xor_sync(0xffffffffu, rs1, 2);
        l0 = l0 * f0 + rs0;
        l1 = l1 * f1 + rs1;

        // ---- pack P hi/lo into A fragments ----
        uint32_t aH[4][4], aL[4][4];
#pragma unroll
        for (int ks2 = 0; ks2 < 4; ks2++) {
            int j0 = 2 * ks2, j1 = 2 * ks2 + 1;
            split2(S[j0][0], S[j0][1], aH[ks2][0], aL[ks2][0]);
            split2(S[j0][2], S[j0][3], aH[ks2][1], aL[ks2][1]);
            split2(S[j1][0], S[j1][1], aH[ks2][2], aL[ks2][2]);
            split2(S[j1][2], S[j1][3], aH[ks2][3], aL[ks2][3]);
        }

        // ---- O += P . V (V fragments via ldmatrix.x4.trans, paired d-blocks) ----
#pragma unroll
        for (int db2 = 0; db2 < 4; db2++) {
#pragma unroll
            for (int ks2 = 0; ks2 < 4; ks2++) {
                uint32_t off = (uint32_t)(((ks2 * 16 + (lane & 15)) * APITCH +
                                           db2 * 16 + ((lane >> 4) & 1) * 8) * 2);
                uint32_t vh[4], vl[4];
                ldsm_x4t(vh, vHi + off);
                ldsm_x4t(vl, vLo + off);
                mma16816(O[2 * db2], aH[ks2], vh);
                mma16816(O[2 * db2], aH[ks2], vl);
                mma16816(O[2 * db2], aL[ks2], vh);
                mma16816(O[2 * db2 + 1], aH[ks2], vh + 2);
                mma16816(O[2 * db2 + 1], aH[ks2], vl + 2);
                mma16816(O[2 * db2 + 1], aL[ks2], vh + 2);
            }
        }

        __syncthreads();
        if (it + 1 < nt) {
            if (it + 2 < nt) {
                load_kv(it & 1, (it + 2) * KT);
                CP_COMMIT();
                CP_WAIT(1);
            } else {
                CP_WAIT(0);
            }
            __syncthreads();
        }
    }

    // ---- normalize and write ----
    float inv0 = 1.f / l0, inv1 = 1.f / l1;
    int row0 = q0 + w * 16 + qr;
#pragma unroll
    for (int db = 0; db < 8; db++) {
        int col = h * DHEAD + db * 8 + qc;
        float2 o0 = make_float2(O[db][0] * inv0, O[db][1] * inv0);
        float2 o1 = make_float2(O[db][2] * inv1, O[db][3] * inv1);
        *(float2*)&out[((size_t)b * LQ + row0) * GN + col] = o0;
        *(float2*)&out[((size_t)b * LQ + row0 + 8) * GN + col] = o1;
    }
}

// ---------------------------------------------------------------------------
extern "C" void kernel_launch(void* const* d_in, const int* in_sizes, int n_in,
                              void* d_out, int out_size) {
    (void)in_sizes;
    (void)n_in;
    (void)out_size;
    const float* Q = (const float*)d_in[0];
    const float* K = (const float*)d_in[1];
    const float* V = (const float*)d_in[2];
    const int* mask = (const int*)d_in[3];
    const float* Wq = (const float*)d_in[4];
    const float* bq = (const float*)d_in[5];
    const float* Wk = (const float*)d_in[6];
    const float* bk = (const float*)d_in[7];
    const float* Wv = (const float*)d_in[8];
    const float* bv = (const float*)d_in[9];
    float* out = (float*)d_out;

    cudaFuncSetAttribute(proj_mma, cudaFuncAttributeMaxDynamicSharedMemorySize, PSMEM_B);
    cudaFuncSetAttribute(attn_mma, cudaFuncAttributeMaxDynamicSharedMemorySize, AT_SMEM);

    __nv_bfloat16 *ahi_p, *alo_p, *whi_p, *wlo_p;
    __nv_bfloat16 *qhi_p, *qlo_p, *khi_p, *klo_p, *vhi_p, *vlo_p;
    cudaGetSymbolAddress((void**)&ahi_p, g_ahi);
    cudaGetSymbolAddress((void**)&alo_p, g_alo);
    cudaGetSymbolAddress((void**)&whi_p, g_whi);
    cudaGetSymbolAddress((void**)&wlo_p, g_wlo);
    cudaGetSymbolAddress((void**)&qhi_p, g_qhi);
    cudaGetSymbolAddress((void**)&qlo_p, g_qlo);
    cudaGetSymbolAddress((void**)&khi_p, g_khi);
    cudaGetSymbolAddress((void**)&klo_p, g_klo);
    cudaGetSymbolAddress((void**)&vhi_p, g_vhi);
    cudaGetSymbolAddress((void**)&vlo_p, g_vlo);

    const int n4 = GM * GK / 4;
    dim3 tg(GN / 32, GK / 32);
    dim3 gg(GN / PBN, GM / PBM);

    mask_scan<<<BATCH, 256>>>(mask);

    const float* X[3] = {Q, K, V};
    const float* W[3] = {Wq, Wk, Wv};
    const float* Bv[3] = {bq, bk, bv};
    __nv_bfloat16* Ch[3] = {qhi_p, khi_p, vhi_p};
    __nv_bfloat16* Cl[3] = {qlo_p, klo_p, vlo_p};
    for (int i = 0; i < 3; i++) {
        wtrans_kernel<<<tg, 256>>>(W[i], whi_p, wlo_p);
        split_kernel<<<(n4 + 255) / 256, 256>>>(X[i], (uint2*)ahi_p, (uint2*)alo_p, n4);
        proj_mma<<<gg, 256, PSMEM_B>>>(ahi_p, alo_p, whi_p, wlo_p, Bv[i], Ch[i], Cl[i]);
    }

    gather_kv<<<dim3(LK / KT, NH, BATCH), 256>>>();

    dim3 ag(LQ / AQ, NH, BATCH);
    attn_mma<<<ag, 256, AT_SMEM>>>(out);
}

// round 9
// speedup vs baseline: 2.0036x; 2.0036x over previous
#include <cuda_runtime.h>
#include <cuda_bf16.h>
#include <cstdint>
#include <math.h>

// ---------------------------------------------------------------------------
// Problem constants
// ---------------------------------------------------------------------------
#define BATCH 4
#define NH 16
#define LQ 2048
#define LK 2048
#define DHEAD 64

#define GM 8192            // B*LQ
#define GN 1024            // H*DHEAD
#define GK 1024            // D_MODEL

#define SCALE_L2E 0.1803368801111204f   // (1/8) * log2(e)
#define MASKNEG  -1.442695040e9f        // -1e9 * log2(e)

#define KT 64              // attention key tile

// Scratch. q/k/v projected outputs as bf16 hi/lo.
// Q: full rows [b*LQ + q][1024]. K/V: COMPACT rows [b*LK + j][1024] (j < nv128).
__device__ __nv_bfloat16 g_qhi[GM * GN];
__device__ __nv_bfloat16 g_qlo[GM * GN];
__device__ __nv_bfloat16 g_khi[GM * GN];
__device__ __nv_bfloat16 g_klo[GM * GN];
__device__ __nv_bfloat16 g_vhi[GM * GN];
__device__ __nv_bfloat16 g_vlo[GM * GN];
__device__ __nv_bfloat16 g_ahi[GM * GK];   // GEMM A input (hi)
__device__ __nv_bfloat16 g_alo[GM * GK];   // GEMM A input (lo)
__device__ __nv_bfloat16 g_whi[GN * GK];   // W transposed: [n][k]
__device__ __nv_bfloat16 g_wlo[GN * GK];

// Key compaction state
__device__ int g_idx[BATCH * LK];
__device__ int g_nv[BATCH];     // valid keys
__device__ int g_nvt[BATCH];    // ceil(nv / KT)

// ---------------------------------------------------------------------------
// Helpers (baseline PTX: ldmatrix / mma.sync / cp.async)
// ---------------------------------------------------------------------------
__device__ __forceinline__ uint32_t smem_u32(const void* p) {
    uint32_t a;
    asm("{ .reg .u64 t; cvta.to.shared.u64 t, %1; cvt.u32.u64 %0, t; }"
        : "=r"(a) : "l"(p));
    return a;
}
__device__ __forceinline__ void cp_async16(uint32_t s, const void* g) {
    asm volatile("cp.async.cg.shared.global [%0], [%1], 16;" :: "r"(s), "l"(g));
}
#define CP_COMMIT() asm volatile("cp.async.commit_group;")
#define CP_WAIT(n) asm volatile("cp.async.wait_group %0;" :: "n"(n))

__device__ __forceinline__ void ldsm_x4(uint32_t* r, uint32_t addr) {
    asm volatile("ldmatrix.sync.aligned.m8n8.x4.shared.b16 {%0,%1,%2,%3}, [%4];"
                 : "=r"(r[0]), "=r"(r[1]), "=r"(r[2]), "=r"(r[3]) : "r"(addr));
}
__device__ __forceinline__ void ldsm_x2(uint32_t* r, uint32_t addr) {
    asm volatile("ldmatrix.sync.aligned.m8n8.x2.shared.b16 {%0,%1}, [%2];"
                 : "=r"(r[0]), "=r"(r[1]) : "r"(addr));
}
__device__ __forceinline__ void ldsm_x2t(uint32_t* r, uint32_t addr) {
    asm volatile("ldmatrix.sync.aligned.m8n8.x2.trans.shared.b16 {%0,%1}, [%2];"
                 : "=r"(r[0]), "=r"(r[1]) : "r"(addr));
}
__device__ __forceinline__ void mma16816(float* c, const uint32_t* a, const uint32_t* b) {
    asm volatile(
        "mma.sync.aligned.m16n8k16.row.col.f32.bf16.bf16.f32 "
        "{%0,%1,%2,%3}, {%4,%5,%6,%7}, {%8,%9}, {%0,%1,%2,%3};"
        : "+f"(c[0]), "+f"(c[1]), "+f"(c[2]), "+f"(c[3])
        : "r"(a[0]), "r"(a[1]), "r"(a[2]), "r"(a[3]), "r"(b[0]), "r"(b[1]));
}

// (x,y) -> packed bf16x2 hi and lo residual
__device__ __forceinline__ void split2(float x, float y, uint32_t& h, uint32_t& l) {
    __nv_bfloat162 hh = __floats2bfloat162_rn(x, y);
    float hx = __bfloat162float(hh.x), hy = __bfloat162float(hh.y);
    __nv_bfloat162 ll = __floats2bfloat162_rn(x - hx, y - hy);
    h = *(uint32_t*)&hh;
    l = *(uint32_t*)&ll;
}
__device__ __forceinline__ uint32_t pack2(float a, float b) {
    __nv_bfloat162 t = __floats2bfloat162_rn(a, b);
    return *(uint32_t*)&t;
}

// ---------------------------------------------------------------------------
// Input conversion kernels
// ---------------------------------------------------------------------------
__global__ __launch_bounds__(256) void split_kernel(const float* __restrict__ x,
                                                    uint2* __restrict__ hi,
                                                    uint2* __restrict__ lo, int n4) {
    int i = blockIdx.x * 256 + threadIdx.x;
    if (i >= n4) return;
    float4 v = ((const float4*)x)[i];
    float h0 = __bfloat162float(__float2bfloat16(v.x));
    float h1 = __bfloat162float(__float2bfloat16(v.y));
    float h2 = __bfloat162float(__float2bfloat16(v.z));
    float h3 = __bfloat162float(__float2bfloat16(v.w));
    uint2 H, L;
    H.x = pack2(h0, h1);
    H.y = pack2(h2, h3);
    L.x = pack2(v.x - h0, v.y - h1);
    L.y = pack2(v.z - h2, v.w - h3);
    hi[i] = H;
    lo[i] = L;
}

__global__ __launch_bounds__(256) void wtrans_kernel(const float* __restrict__ W,
                                                     __nv_bfloat16* __restrict__ thi,
                                                     __nv_bfloat16* __restrict__ tlo) {
    __shared__ float t[32][33];
    int n0 = blockIdx.x * 32, k0 = blockIdx.y * 32;
    int tx = threadIdx.x & 31, ty0 = threadIdx.x >> 5;
#pragma unroll
    for (int i = 0; i < 4; i++) {
        int ty = ty0 + i * 8;
        t[ty][tx] = W[(size_t)(k0 + ty) * GN + n0 + tx];
    }
    __syncthreads();
#pragma unroll
    for (int i = 0; i < 4; i++) {
        int ty = ty0 + i * 8;
        float v = t[tx][ty];
        __nv_bfloat16 h = __float2bfloat16(v);
        size_t o = (size_t)(n0 + ty) * GK + k0 + tx;
        thi[o] = h;
        tlo[o] = __float2bfloat16(v - __bfloat162float(h));
    }
}

// ---------------------------------------------------------------------------
// Mask scan: per-batch valid-key index list (block-wide scan, 1 CTA/batch)
// ---------------------------------------------------------------------------
__global__ __launch_bounds__(256) void mask_scan(const int* __restrict__ mask) {
    __shared__ int wsum[8];
    const int b = blockIdx.x;
    const int* m = mask + b * LK;
    const int tid = threadIdx.x;
    const int lane = tid & 31, w = tid >> 5;

    int v[8], s = 0;
#pragma unroll
    for (int i = 0; i < 8; i++) {
        v[i] = (m[tid * 8 + i] != 0);
        s += v[i];
    }
    int ps = s;
#pragma unroll
    for (int o = 1; o < 32; o <<= 1) {
        int t = __shfl_up_sync(0xffffffffu, ps, o);
        if (lane >= o) ps += t;
    }
    if (lane == 31) wsum[w] = ps;
    __syncthreads();
    if (w == 0) {
        int t = (lane < 8) ? wsum[lane] : 0;
#pragma unroll
        for (int o = 1; o < 8; o <<= 1) {
            int u = __shfl_up_sync(0xffffffffu, t, o);
            if (lane >= o) t += u;
        }
        if (lane < 8) wsum[lane] = t;
    }
    __syncthreads();
    int excl = ps - s + (w ? wsum[w - 1] : 0);
#pragma unroll
    for (int i = 0; i < 8; i++) {
        if (v[i]) g_idx[b * LK + excl++] = tid * 8 + i;
    }
    if (tid == 255) {
        int nv = wsum[7];
        g_nv[b] = nv;
        g_nvt[b] = (nv + KT - 1) / KT;
    }
}

// ---------------------------------------------------------------------------
// Gather valid input rows (coalesced full-row copies) + bf16 split.
// Writes compact rows [b*LK + j][1024] to g_ahi/g_alo, zero-padded to nv128.
// ---------------------------------------------------------------------------
__global__ __launch_bounds__(256) void gather_split(const float* __restrict__ X) {
    const int b = blockIdx.y;
    const int nv = g_nv[b];
    const int nv128 = (nv + 127) & ~127;
    const int j0 = blockIdx.x * 8;
    if (j0 >= nv128) return;
    const int tid = threadIdx.x;

#pragma unroll
    for (int i = 0; i < 8; i++) {
        int j = j0 + i;
        if (j >= nv128) break;
        uint2 H = make_uint2(0, 0), L = make_uint2(0, 0);
        if (j < nv) {
            int s = g_idx[b * LK + j];
            float4 v = *(const float4*)(X + ((size_t)b * LK + s) * GK + tid * 4);
            float h0 = __bfloat162float(__float2bfloat16(v.x));
            float h1 = __bfloat162float(__float2bfloat16(v.y));
            float h2 = __bfloat162float(__float2bfloat16(v.z));
            float h3 = __bfloat162float(__float2bfloat16(v.w));
            H.x = pack2(h0, h1);
            H.y = pack2(h2, h3);
            L.x = pack2(v.x - h0, v.y - h1);
            L.y = pack2(v.z - h2, v.w - h3);
        }
        size_t o = ((size_t)b * LK + j) * GK + tid * 4;
        *(uint2*)(g_ahi + o) = H;
        *(uint2*)(g_alo + o) = L;
    }
}

// ---------------------------------------------------------------------------
// Projection GEMM (mma.sync, bf16 hi/lo 3-term), 2 CTAs/SM.
// COMPACT: per-batch row tiles beyond nv128 early-exit.
// ---------------------------------------------------------------------------
#define PBM 128
#define PBN 128
#define PBK 32
#define PPITCH 40
#define PTILE_B (128 * PPITCH * 2)
#define POFF_AHI 0
#define POFF_ALO (POFF_AHI + PTILE_B)
#define POFF_BHI (POFF_ALO + PTILE_B)
#define POFF_BLO (POFF_BHI + PTILE_B)
#define PSTAGE_B (4 * PTILE_B)
#define PSMEM_B (2 * PSTAGE_B)
#define PNCHUNK (GK / PBK)

template <bool COMPACT>
__global__ __launch_bounds__(256, 2) void proj_mma(const __nv_bfloat16* __restrict__ Ahi,
                                                   const __nv_bfloat16* __restrict__ Alo,
                                                   const __nv_bfloat16* __restrict__ Bhi,
                                                   const __nv_bfloat16* __restrict__ Blo,
                                                   const float* __restrict__ bias,
                                                   __nv_bfloat16* __restrict__ Chi,
                                                   __nv_bfloat16* __restrict__ Clo) {
    const int rowBase = blockIdx.y * PBM;
    if (COMPACT) {
        int b = rowBase / LQ;                   // 16 tiles per batch
        int nv128 = (g_nv[b] + 127) & ~127;
        if ((rowBase % LQ) >= nv128) return;    // nothing valid in this tile
    }

    extern __shared__ char smem[];
    const uint32_t sb = smem_u32(smem);
    const int tid = threadIdx.x;
    const int lane = tid & 31;
    const int warp = tid >> 5;
    const int wm = warp & 1;
    const int wn = warp >> 1;
    const int colBase = blockIdx.x * PBN;

    float acc[4][4][4];
#pragma unroll
    for (int i = 0; i < 4; i++)
#pragma unroll
        for (int j = 0; j < 4; j++)
#pragma unroll
            for (int r = 0; r < 4; r++) acc[i][j][r] = 0.f;

    auto load_chunk = [&](int stage, int kb) {
        uint32_t s0 = sb + stage * PSTAGE_B;
#pragma unroll
        for (int i = 0; i < 2; i++) {
            int c = tid + i * 256;
            int r = c >> 2;
            int col = (c & 3) * 8;
            uint32_t so = (uint32_t)(r * (PPITCH * 2) + col * 2);
            size_t ga = (size_t)(rowBase + r) * GK + kb + col;
            size_t gb = (size_t)(colBase + r) * GK + kb + col;
            cp_async16(s0 + POFF_AHI + so, Ahi + ga);
            cp_async16(s0 + POFF_ALO + so, Alo + ga);
            cp_async16(s0 + POFF_BHI + so, Bhi + gb);
            cp_async16(s0 + POFF_BLO + so, Blo + gb);
        }
    };

    const int lr = lane & 7;
    const int lgA_m = ((lane >> 3) & 1) * 8;
    const int lgA_k = (lane >> 4) * 8;
    const int lgB_k = ((lane >> 3) & 1) * 8;

    load_chunk(0, 0);
    CP_COMMIT();

    for (int ch = 0; ch < PNCHUNK; ch++) {
        if (ch + 1 < PNCHUNK) {
            load_chunk((ch + 1) & 1, (ch + 1) * PBK);
            CP_COMMIT();
            CP_WAIT(1);
        } else {
            CP_WAIT(0);
        }
        __syncthreads();

        const uint32_t s0 = sb + (ch & 1) * PSTAGE_B;
        const uint32_t aHi = s0 + POFF_AHI, aLo = s0 + POFF_ALO;
        const uint32_t bHi = s0 + POFF_BHI, bLo = s0 + POFF_BLO;

#pragma unroll
        for (int ks = 0; ks < PBK; ks += 16) {
            uint32_t ahi[4][4], alo[4][4];
#pragma unroll
            for (int mt = 0; mt < 4; mt++) {
                int row = wm * 64 + mt * 16 + lgA_m + lr;
                uint32_t off = (uint32_t)(row * (PPITCH * 2) + (ks + lgA_k) * 2);
                ldsm_x4(ahi[mt], aHi + off);
                ldsm_x4(alo[mt], aLo + off);
            }
#pragma unroll
            for (int nt = 0; nt < 4; nt++) {
                int brow = wn * 32 + nt * 8 + lr;
                uint32_t off = (uint32_t)(brow * (PPITCH * 2) + (ks + lgB_k) * 2);
                uint32_t bh[2], bl[2];
                ldsm_x2(bh, bHi + off);
                ldsm_x2(bl, bLo + off);
#pragma unroll
                for (int mt = 0; mt < 4; mt++) {
                    mma16816(acc[mt][nt], ahi[mt], bh);
                    mma16816(acc[mt][nt], ahi[mt], bl);
                    mma16816(acc[mt][nt], alo[mt], bh);
                }
            }
        }
        __syncthreads();
    }

    // Epilogue: bias add, split to bf16 hi/lo, store
#pragma unroll
    for (int mt = 0; mt < 4; mt++) {
#pragma unroll
        for (int nt = 0; nt < 4; nt++) {
            int row = rowBase + wm * 64 + mt * 16 + (lane >> 2);
            int col = colBase + wn * 32 + nt * 8 + (lane & 3) * 2;
            float2 bb = *(const float2*)&bias[col];
            float v0 = acc[mt][nt][0] + bb.x, v1 = acc[mt][nt][1] + bb.y;
            float v2 = acc[mt][nt][2] + bb.x, v3 = acc[mt][nt][3] + bb.y;
            uint32_t h, l;
            split2(v0, v1, h, l);
            *(uint32_t*)(Chi + (size_t)row * GN + col) = h;
            *(uint32_t*)(Clo + (size_t)row * GN + col) = l;
            split2(v2, v3, h, l);
            *(uint32_t*)(Chi + (size_t)(row + 8) * GN + col) = h;
            *(uint32_t*)(Clo + (size_t)(row + 8) * GN + col) = l;
        }
    }
}

// ---------------------------------------------------------------------------
// Flash attention on mma.sync with compacted keys.
// R6-verified inner loop (x2/x2t ldsm); dynamic tile count; register tail mask.
// ---------------------------------------------------------------------------
#define AQ 128
#define APITCH 72                       // bf16 elems per smem row (144 B)
#define AT_QH 0
#define AT_QL (AT_QH + AQ * APITCH * 2)             // 18432
#define AT_ST (AT_QL + AQ * APITCH * 2)             // 36864
#define AT_ARR (KT * APITCH * 2)                    // 9216
#define AT_STG (4 * AT_ARR)                         // 36864
#define AT_SMEM (AT_ST + 2 * AT_STG)                // 110592

__global__ __launch_bounds__(256) void attn_mma(float* __restrict__ out) {
    extern __shared__ char smem[];
    const uint32_t sb = smem_u32(smem);

    const int tid = threadIdx.x;
    const int lane = tid & 31;
    const int w = tid >> 5;
    const int q0 = blockIdx.x * AQ;
    const int h = blockIdx.y;
    const int b = blockIdx.z;

    const int nv = g_nv[b];
    const int nt = g_nvt[b];

    const int lr = lane & 7;
    const int lgA_m = ((lane >> 3) & 1) * 8;
    const int lgA_k = (lane >> 4) * 8;
    const int lgB_k = ((lane >> 3) & 1) * 8;
    const int qr = lane >> 2;
    const int qc = (lane & 3) * 2;

    // ---- prologue: q tile + kv tiles 0/1 ----
    const size_t hoff = (size_t)h * DHEAD;
#pragma unroll
    for (int i = 0; i < 8; i++) {
        int seg = tid + i * 256;
        int arr = seg >> 10;
        int s2 = seg & 1023;
        int row = s2 >> 3, c8 = (s2 & 7) * 8;
        const __nv_bfloat16* g = (arr ? g_qlo : g_qhi) +
            (((size_t)b * LQ + q0 + row) * NH) * DHEAD + hoff + c8;
        cp_async16(sb + (arr ? AT_QL : AT_QH) + (uint32_t)((row * APITCH + c8) * 2), g);
    }

    auto load_kv = [&](int stage, int kt) {
        uint32_t s0 = sb + AT_ST + stage * AT_STG;
#pragma unroll
        for (int i = 0; i < 2; i++) {
            int seg = tid + i * 256;
            int row = seg >> 3, c8 = (seg & 7) * 8;
            size_t go = (((size_t)b * LK + kt + row) * NH) * DHEAD + hoff + c8;
            uint32_t so = (uint32_t)((row * APITCH + c8) * 2);
            cp_async16(s0 + 0 * AT_ARR + so, g_khi + go);
            cp_async16(s0 + 1 * AT_ARR + so, g_klo + go);
            cp_async16(s0 + 2 * AT_ARR + so, g_vhi + go);
            cp_async16(s0 + 3 * AT_ARR + so, g_vlo + go);
        }
    };
    load_kv(0, 0);
    CP_COMMIT();
    if (nt > 1) {
        load_kv(1, KT);
        CP_COMMIT();
        CP_WAIT(1);
    } else {
        CP_WAIT(0);
    }
    __syncthreads();

    // ---- q fragments ----
    uint32_t qh[4][4], ql[4][4];
#pragma unroll
    for (int ks = 0; ks < 4; ks++) {
        uint32_t off = (uint32_t)(((w * 16 + lgA_m + lr) * APITCH + ks * 16 + lgA_k) * 2);
        ldsm_x4(qh[ks], sb + AT_QH + off);
        ldsm_x4(ql[ks], sb + AT_QL + off);
    }

    float O[8][4];
#pragma unroll
    for (int d = 0; d < 8; d++) O[d][0] = O[d][1] = O[d][2] = O[d][3] = 0.f;
    float m0 = -INFINITY, m1 = -INFINITY, l0 = 0.f, l1 = 0.f;

    for (int it = 0; it < nt; it++) {
        const uint32_t s0 = sb + AT_ST + (it & 1) * AT_STG;
        const uint32_t kHi = s0, kLo = s0 + AT_ARR;
        const uint32_t vHi = s0 + 2 * AT_ARR, vLo = s0 + 3 * AT_ARR;
        const int ktb = it * KT;

        // ---- S = q . k^T ----
        float S[8][4];
#pragma unroll
        for (int nb = 0; nb < 8; nb++)
            S[nb][0] = S[nb][1] = S[nb][2] = S[nb][3] = 0.f;
#pragma unroll
        for (int ks = 0; ks < 4; ks++) {
#pragma unroll
            for (int nb = 0; nb < 8; nb++) {
                uint32_t off = (uint32_t)(((nb * 8 + lr) * APITCH + ks * 16 + lgB_k) * 2);
                uint32_t kh[2], kl[2];
                ldsm_x2(kh, kHi + off);
                ldsm_x2(kl, kLo + off);
                mma16816(S[nb], qh[ks], kh);
                mma16816(S[nb], qh[ks], kl);
                mma16816(S[nb], ql[ks], kh);
            }
        }

        // ---- scale + tail mask (register compare; exact) ----
#pragma unroll
        for (int nb = 0; nb < 8; nb++) {
            int p0 = ktb + nb * 8 + qc;
            bool v0 = p0 < nv, v1 = p0 + 1 < nv;
            S[nb][0] = v0 ? S[nb][0] * SCALE_L2E : MASKNEG;
            S[nb][1] = v1 ? S[nb][1] * SCALE_L2E : MASKNEG;
            S[nb][2] = v0 ? S[nb][2] * SCALE_L2E : MASKNEG;
            S[nb][3] = v1 ? S[nb][3] * SCALE_L2E : MASKNEG;
        }

        // ---- online softmax ----
        float tm0 = -INFINITY, tm1 = -INFINITY;
#pragma unroll
        for (int nb = 0; nb < 8; nb++) {
            tm0 = fmaxf(tm0, fmaxf(S[nb][0], S[nb][1]));
            tm1 = fmaxf(tm1, fmaxf(S[nb][2], S[nb][3]));
        }
        tm0 = fmaxf(tm0, __shfl_xor_sync(0xffffffffu, tm0, 1));
        tm0 = fmaxf(tm0, __shfl_xor_sync(0xffffffffu, tm0, 2));
        tm1 = fmaxf(tm1, __shfl_xor_sync(0xffffffffu, tm1, 1));
        tm1 = fmaxf(tm1, __shfl_xor_sync(0xffffffffu, tm1, 2));
        float m0n = fmaxf(m0, tm0), m1n = fmaxf(m1, tm1);
        float f0 = exp2f(m0 - m0n), f1 = exp2f(m1 - m1n);
        m0 = m0n;
        m1 = m1n;
#pragma unroll
        for (int d = 0; d < 8; d++) {
            O[d][0] *= f0;
            O[d][1] *= f0;
            O[d][2] *= f1;
            O[d][3] *= f1;
        }
        float rs0 = 0.f, rs1 = 0.f;
#pragma unroll
        for (int nb = 0; nb < 8; nb++) {
            S[nb][0] = exp2f(S[nb][0] - m0);
            S[nb][1] = exp2f(S[nb][1] - m0);
            S[nb][2] = exp2f(S[nb][2] - m1);
            S[nb][3] = exp2f(S[nb][3] - m1);
            rs0 += S[nb][0] + S[nb][1];
            rs1 += S[nb][2] + S[nb][3];
        }
        rs0 += __shfl_xor_sync(0xffffffffu, rs0, 1);
        rs0 += __shfl_xor_sync(0xffffffffu, rs0, 2);
        rs1 += __shfl_xor_sync(0xffffffffu, rs1, 1);
        rs1 += __shfl_xor_sync(0xffffffffu, rs1, 2);
        l0 = l0 * f0 + rs0;
        l1 = l1 * f1 + rs1;

        // ---- pack P hi/lo into A fragments ----
        uint32_t aH[4][4], aL[4][4];
#pragma unroll
        for (int ks2 = 0; ks2 < 4; ks2++) {
            int j0 = 2 * ks2, j1 = 2 * ks2 + 1;
            split2(S[j0][0], S[j0][1], aH[ks2][0], aL[ks2][0]);
            split2(S[j0][2], S[j0][3], aH[ks2][1], aL[ks2][1]);
            split2(S[j1][0], S[j1][1], aH[ks2][2], aL[ks2][2]);
            split2(S[j1][2], S[j1][3], aH[ks2][3], aL[ks2][3]);
        }

        // ---- O += P . V ----
#pragma unroll
        for (int db = 0; db < 8; db++) {
#pragma unroll
            for (int ks2 = 0; ks2 < 4; ks2++) {
                uint32_t off = (uint32_t)(((ks2 * 16 + (lane & 15)) * APITCH + db * 8) * 2);
                uint32_t vh[2], vl[2];
                ldsm_x2t(vh, vHi + off);
                ldsm_x2t(vl, vLo + off);
                mma16816(O[db], aH[ks2], vh);
                mma16816(O[db], aH[ks2], vl);
                mma16816(O[db], aL[ks2], vh);
            }
        }

        __syncthreads();
        if (it + 1 < nt) {
            if (it + 2 < nt) {
                load_kv(it & 1, (it + 2) * KT);
                CP_COMMIT();
                CP_WAIT(1);
            } else {
                CP_WAIT(0);
            }
            __syncthreads();
        }
    }

    // ---- normalize and write ----
    float inv0 = 1.f / l0, inv1 = 1.f / l1;
    int row0 = q0 + w * 16 + qr;
#pragma unroll
    for (int db = 0; db < 8; db++) {
        int col = h * DHEAD + db * 8 + qc;
        float2 o0 = make_float2(O[db][0] * inv0, O[db][1] * inv0);
        float2 o1 = make_float2(O[db][2] * inv1, O[db][3] * inv1);
        *(float2*)&out[((size_t)b * LQ + row0) * GN + col] = o0;
        *(float2*)&out[((size_t)b * LQ + row0 + 8) * GN + col] = o1;
    }
}

// ---------------------------------------------------------------------------
extern "C" void kernel_launch(void* const* d_in, const int* in_sizes, int n_in,
                              void* d_out, int out_size) {
    (void)in_sizes;
    (void)n_in;
    (void)out_size;
    const float* Q = (const float*)d_in[0];
    const float* K = (const float*)d_in[1];
    const float* V = (const float*)d_in[2];
    const int* mask = (const int*)d_in[3];
    const float* Wq = (const float*)d_in[4];
    const float* bq = (const float*)d_in[5];
    const float* Wk = (const float*)d_in[6];
    const float* bk = (const float*)d_in[7];
    const float* Wv = (const float*)d_in[8];
    const float* bv = (const float*)d_in[9];
    float* out = (float*)d_out;

    cudaFuncSetAttribute(proj_mma<false>, cudaFuncAttributeMaxDynamicSharedMemorySize,
                         PSMEM_B);
    cudaFuncSetAttribute(proj_mma<true>, cudaFuncAttributeMaxDynamicSharedMemorySize,
                         PSMEM_B);
    cudaFuncSetAttribute(attn_mma, cudaFuncAttributeMaxDynamicSharedMemorySize, AT_SMEM);

    __nv_bfloat16 *ahi_p, *alo_p, *whi_p, *wlo_p;
    __nv_bfloat16 *qhi_p, *qlo_p, *khi_p, *klo_p, *vhi_p, *vlo_p;
    cudaGetSymbolAddress((void**)&ahi_p, g_ahi);
    cudaGetSymbolAddress((void**)&alo_p, g_alo);
    cudaGetSymbolAddress((void**)&whi_p, g_whi);
    cudaGetSymbolAddress((void**)&wlo_p, g_wlo);
    cudaGetSymbolAddress((void**)&qhi_p, g_qhi);
    cudaGetSymbolAddress((void**)&qlo_p, g_qlo);
    cudaGetSymbolAddress((void**)&khi_p, g_khi);
    cudaGetSymbolAddress((void**)&klo_p, g_klo);
    cudaGetSymbolAddress((void**)&vhi_p, g_vhi);
    cudaGetSymbolAddress((void**)&vlo_p, g_vlo);

    const int n4 = GM * GK / 4;
    dim3 tg(GN / 32, GK / 32);
    dim3 gg(GN / PBN, GM / PBM);        // (8, 64)
    dim3 gsg(LK / 8, BATCH);            // gather_split grid

    mask_scan<<<BATCH, 256>>>(mask);

    // Q: full projection
    wtrans_kernel<<<tg, 256>>>(Wq, whi_p, wlo_p);
    split_kernel<<<(n4 + 255) / 256, 256>>>(Q, (uint2*)ahi_p, (uint2*)alo_p, n4);
    proj_mma<false><<<gg, 256, PSMEM_B>>>(ahi_p, alo_p, whi_p, wlo_p, bq, qhi_p, qlo_p);

    // K: compact rows, then projection over valid tiles only
    wtrans_kernel<<<tg, 256>>>(Wk, whi_p, wlo_p);
    gather_split<<<gsg, 256>>>(K);
    proj_mma<true><<<gg, 256, PSMEM_B>>>(ahi_p, alo_p, whi_p, wlo_p, bk, khi_p, klo_p);

    // V: compact rows, then projection over valid tiles only
    wtrans_kernel<<<tg, 256>>>(Wv, whi_p, wlo_p);
    gather_split<<<gsg, 256>>>(V);
    proj_mma<true><<<gg, 256, PSMEM_B>>>(ahi_p, alo_p, whi_p, wlo_p, bv, vhi_p, vlo_p);

    dim3 ag(LQ / AQ, NH, BATCH);
    attn_mma<<<ag, 256, AT_SMEM>>>(out);
}

// round 10
// speedup vs baseline: 2.0416x; 1.0190x over previous
#include <cuda_runtime.h>
#include <cuda_bf16.h>
#include <cstdint>
#include <math.h>

// ---------------------------------------------------------------------------
// Problem constants
// ---------------------------------------------------------------------------
#define BATCH 4
#define NH 16
#define LQ 2048
#define LK 2048
#define DHEAD 64

#define GM 8192            // B*LQ
#define GN 1024            // H*DHEAD
#define GK 1024            // D_MODEL

#define SCALE_L2E 0.1803368801111204f   // (1/8) * log2(e)
#define MASKNEG  -1.442695040e9f        // -1e9 * log2(e)

#define KT 64              // attention key tile

// Scratch. q/k/v projected outputs as bf16 hi/lo.
// Q: full rows [b*LQ + q][1024]. K/V: COMPACT rows [b*LK + j][1024] (j < nv128).
__device__ __nv_bfloat16 g_qhi[GM * GN];
__device__ __nv_bfloat16 g_qlo[GM * GN];
__device__ __nv_bfloat16 g_khi[GM * GN];
__device__ __nv_bfloat16 g_klo[GM * GN];
__device__ __nv_bfloat16 g_vhi[GM * GN];
__device__ __nv_bfloat16 g_vlo[GM * GN];
// GEMM A inputs: z=0 (Q split, full), z=1 (K gathered), z=2 (V gathered)
__device__ __nv_bfloat16 g_ahi[GM * GK];
__device__ __nv_bfloat16 g_alo[GM * GK];
__device__ __nv_bfloat16 g_kinh[GM * GK];
__device__ __nv_bfloat16 g_kinl[GM * GK];
__device__ __nv_bfloat16 g_vinh[GM * GK];
__device__ __nv_bfloat16 g_vinl[GM * GK];
// W transposed [z][n][k]
__device__ __nv_bfloat16 g_whi[3 * GN * GK];
__device__ __nv_bfloat16 g_wlo[3 * GN * GK];

// Key compaction state
__device__ int g_idx[BATCH * LK];
__device__ int g_nv[BATCH];     // valid keys
__device__ int g_nvt[BATCH];    // ceil(nv / KT)

// ---------------------------------------------------------------------------
// Helpers (baseline PTX: ldmatrix / mma.sync / cp.async)
// ---------------------------------------------------------------------------
__device__ __forceinline__ uint32_t smem_u32(const void* p) {
    uint32_t a;
    asm("{ .reg .u64 t; cvta.to.shared.u64 t, %1; cvt.u32.u64 %0, t; }"
        : "=r"(a) : "l"(p));
    return a;
}
__device__ __forceinline__ void cp_async16(uint32_t s, const void* g) {
    asm volatile("cp.async.cg.shared.global [%0], [%1], 16;" :: "r"(s), "l"(g));
}
#define CP_COMMIT() asm volatile("cp.async.commit_group;")
#define CP_WAIT(n) asm volatile("cp.async.wait_group %0;" :: "n"(n))

__device__ __forceinline__ void ldsm_x4(uint32_t* r, uint32_t addr) {
    asm volatile("ldmatrix.sync.aligned.m8n8.x4.shared.b16 {%0,%1,%2,%3}, [%4];"
                 : "=r"(r[0]), "=r"(r[1]), "=r"(r[2]), "=r"(r[3]) : "r"(addr));
}
__device__ __forceinline__ void ldsm_x2(uint32_t* r, uint32_t addr) {
    asm volatile("ldmatrix.sync.aligned.m8n8.x2.shared.b16 {%0,%1}, [%2];"
                 : "=r"(r[0]), "=r"(r[1]) : "r"(addr));
}
__device__ __forceinline__ void ldsm_x2t(uint32_t* r, uint32_t addr) {
    asm volatile("ldmatrix.sync.aligned.m8n8.x2.trans.shared.b16 {%0,%1}, [%2];"
                 : "=r"(r[0]), "=r"(r[1]) : "r"(addr));
}
__device__ __forceinline__ void mma16816(float* c, const uint32_t* a, const uint32_t* b) {
    asm volatile(
        "mma.sync.aligned.m16n8k16.row.col.f32.bf16.bf16.f32 "
        "{%0,%1,%2,%3}, {%4,%5,%6,%7}, {%8,%9}, {%0,%1,%2,%3};"
        : "+f"(c[0]), "+f"(c[1]), "+f"(c[2]), "+f"(c[3])
        : "r"(a[0]), "r"(a[1]), "r"(a[2]), "r"(a[3]), "r"(b[0]), "r"(b[1]));
}

// (x,y) -> packed bf16x2 hi and lo residual
__device__ __forceinline__ void split2(float x, float y, uint32_t& h, uint32_t& l) {
    __nv_bfloat162 hh = __floats2bfloat162_rn(x, y);
    float hx = __bfloat162float(hh.x), hy = __bfloat162float(hh.y);
    __nv_bfloat162 ll = __floats2bfloat162_rn(x - hx, y - hy);
    h = *(uint32_t*)&hh;
    l = *(uint32_t*)&ll;
}
__device__ __forceinline__ uint32_t pack2(float a, float b) {
    __nv_bfloat162 t = __floats2bfloat162_rn(a, b);
    return *(uint32_t*)&t;
}

// ---------------------------------------------------------------------------
// Mask scan: per-batch valid-key index list (block-wide scan, 1 CTA/batch)
// ---------------------------------------------------------------------------
__global__ __launch_bounds__(256) void mask_scan(const int* __restrict__ mask) {
    __shared__ int wsum[8];
    const int b = blockIdx.x;
    const int* m = mask + b * LK;
    const int tid = threadIdx.x;
    const int lane = tid & 31, w = tid >> 5;

    int v[8], s = 0;
#pragma unroll
    for (int i = 0; i < 8; i++) {
        v[i] = (m[tid * 8 + i] != 0);
        s += v[i];
    }
    int ps = s;
#pragma unroll
    for (int o = 1; o < 32; o <<= 1) {
        int t = __shfl_up_sync(0xffffffffu, ps, o);
        if (lane >= o) ps += t;
    }
    if (lane == 31) wsum[w] = ps;
    __syncthreads();
    if (w == 0) {
        int t = (lane < 8) ? wsum[lane] : 0;
#pragma unroll
        for (int o = 1; o < 8; o <<= 1) {
            int u = __shfl_up_sync(0xffffffffu, t, o);
            if (lane >= o) t += u;
        }
        if (lane < 8) wsum[lane] = t;
    }
    __syncthreads();
    int excl = ps - s + (w ? wsum[w - 1] : 0);
#pragma unroll
    for (int i = 0; i < 8; i++) {
        if (v[i]) g_idx[b * LK + excl++] = tid * 8 + i;
    }
    if (tid == 255) {
        int nv = wsum[7];
        g_nv[b] = nv;
        g_nvt[b] = (nv + KT - 1) / KT;
    }
}

// ---------------------------------------------------------------------------
// wtrans3: W[z] [k][n] fp32 -> g_whi/g_wlo[z] bf16 [n][k]. z = blockIdx.z.
// ---------------------------------------------------------------------------
__global__ __launch_bounds__(256) void wtrans3(const float* __restrict__ W0,
                                               const float* __restrict__ W1,
                                               const float* __restrict__ W2) {
    __shared__ float t[32][33];
    const int z = blockIdx.z;
    const float* W = (z == 0) ? W0 : (z == 1) ? W1 : W2;
    __nv_bfloat16* thi = g_whi + (size_t)z * GN * GK;
    __nv_bfloat16* tlo = g_wlo + (size_t)z * GN * GK;

    int n0 = blockIdx.x * 32, k0 = blockIdx.y * 32;
    int tx = threadIdx.x & 31, ty0 = threadIdx.x >> 5;
#pragma unroll
    for (int i = 0; i < 4; i++) {
        int ty = ty0 + i * 8;
        t[ty][tx] = W[(size_t)(k0 + ty) * GN + n0 + tx];
    }
    __syncthreads();
#pragma unroll
    for (int i = 0; i < 4; i++) {
        int ty = ty0 + i * 8;
        float v = t[tx][ty];
        __nv_bfloat16 h = __float2bfloat16(v);
        size_t o = (size_t)(n0 + ty) * GK + k0 + tx;
        thi[o] = h;
        tlo[o] = __float2bfloat16(v - __bfloat162float(h));
    }
}

// ---------------------------------------------------------------------------
// prep3: z=0 split Q (full); z=1 gather+split K; z=2 gather+split V.
// Grid (8192, 3). Gather z uses only first 1024 blocks.
// ---------------------------------------------------------------------------
__global__ __launch_bounds__(256) void prep3(const float* __restrict__ Q,
                                             const float* __restrict__ K,
                                             const float* __restrict__ V) {
    const int z = blockIdx.z;
    const int tid = threadIdx.x;

    if (z == 0) {
        int i = blockIdx.x * 256 + tid;      // n4 = GM*GK/4 = 2M = 8192*256
        float4 v = ((const float4*)Q)[i];
        float h0 = __bfloat162float(__float2bfloat16(v.x));
        float h1 = __bfloat162float(__float2bfloat16(v.y));
        float h2 = __bfloat162float(__float2bfloat16(v.z));
        float h3 = __bfloat162float(__float2bfloat16(v.w));
        uint2 H, L;
        H.x = pack2(h0, h1);
        H.y = pack2(h2, h3);
        L.x = pack2(v.x - h0, v.y - h1);
        L.y = pack2(v.z - h2, v.w - h3);
        ((uint2*)g_ahi)[i] = H;
        ((uint2*)g_alo)[i] = L;
        return;
    }

    const int x = blockIdx.x;
    if (x >= 256 * BATCH) return;
    const int b = x >> 8;
    const int j0 = (x & 255) * 8;
    const int nv = g_nv[b];
    const int nv128 = (nv + 127) & ~127;
    if (j0 >= nv128) return;

    const float* X = (z == 1) ? K : V;
    __nv_bfloat16* dh = (z == 1) ? g_kinh : g_vinh;
    __nv_bfloat16* dl = (z == 1) ? g_kinl : g_vinl;

#pragma unroll
    for (int i = 0; i < 8; i++) {
        int j = j0 + i;
        if (j >= nv128) break;
        uint2 H = make_uint2(0, 0), L = make_uint2(0, 0);
        if (j < nv) {
            int s = g_idx[b * LK + j];
            float4 v = *(const float4*)(X + ((size_t)b * LK + s) * GK + tid * 4);
            float h0 = __bfloat162float(__float2bfloat16(v.x));
            float h1 = __bfloat162float(__float2bfloat16(v.y));
            float h2 = __bfloat162float(__float2bfloat16(v.z));
            float h3 = __bfloat162float(__float2bfloat16(v.w));
            H.x = pack2(h0, h1);
            H.y = pack2(h2, h3);
            L.x = pack2(v.x - h0, v.y - h1);
            L.y = pack2(v.z - h2, v.w - h3);
        }
        size_t o = ((size_t)b * LK + j) * GK + tid * 4;
        *(uint2*)(dh + o) = H;
        *(uint2*)(dl + o) = L;
    }
}

// ---------------------------------------------------------------------------
// proj3: fused projection GEMMs (mma.sync, bf16 hi/lo 3-term), 2 CTAs/SM.
// Grid (8, 64, 3): z=0 Q (full), z=1 K (compact), z=2 V (compact).
// ---------------------------------------------------------------------------
#define PBM 128
#define PBN 128
#define PBK 32
#define PPITCH 40
#define PTILE_B (128 * PPITCH * 2)
#define POFF_AHI 0
#define POFF_ALO (POFF_AHI + PTILE_B)
#define POFF_BHI (POFF_ALO + PTILE_B)
#define POFF_BLO (POFF_BHI + PTILE_B)
#define PSTAGE_B (4 * PTILE_B)
#define PSMEM_B (2 * PSTAGE_B)
#define PNCHUNK (GK / PBK)

__global__ __launch_bounds__(256, 2) void proj3(const float* __restrict__ bq,
                                                const float* __restrict__ bk,
                                                const float* __restrict__ bv) {
    const int z = blockIdx.z;
    const int rowBase = blockIdx.y * PBM;
    if (z > 0) {
        int b = rowBase / LQ;                   // 16 tiles per batch
        int nv128 = (g_nv[b] + 127) & ~127;
        if ((rowBase % LQ) >= nv128) return;    // nothing valid in this tile
    }

    const __nv_bfloat16* Ahi = (z == 0) ? g_ahi : (z == 1) ? g_kinh : g_vinh;
    const __nv_bfloat16* Alo = (z == 0) ? g_alo : (z == 1) ? g_kinl : g_vinl;
    const __nv_bfloat16* Bhi = g_whi + (size_t)z * GN * GK;
    const __nv_bfloat16* Blo = g_wlo + (size_t)z * GN * GK;
    const float* bias = (z == 0) ? bq : (z == 1) ? bk : bv;
    __nv_bfloat16* Chi = (z == 0) ? g_qhi : (z == 1) ? g_khi : g_vhi;
    __nv_bfloat16* Clo = (z == 0) ? g_qlo : (z == 1) ? g_klo : g_vlo;

    extern __shared__ char smem[];
    const uint32_t sb = smem_u32(smem);
    const int tid = threadIdx.x;
    const int lane = tid & 31;
    const int warp = tid >> 5;
    const int wm = warp & 1;
    const int wn = warp >> 1;
    const int colBase = blockIdx.x * PBN;

    float acc[4][4][4];
#pragma unroll
    for (int i = 0; i < 4; i++)
#pragma unroll
        for (int j = 0; j < 4; j++)
#pragma unroll
            for (int r = 0; r < 4; r++) acc[i][j][r] = 0.f;

    auto load_chunk = [&](int stage, int kb) {
        uint32_t s0 = sb + stage * PSTAGE_B;
#pragma unroll
        for (int i = 0; i < 2; i++) {
            int c = tid + i * 256;
            int r = c >> 2;
            int col = (c & 3) * 8;
            uint32_t so = (uint32_t)(r * (PPITCH * 2) + col * 2);
            size_t ga = (size_t)(rowBase + r) * GK + kb + col;
            size_t gb = (size_t)(colBase + r) * GK + kb + col;
            cp_async16(s0 + POFF_AHI + so, Ahi + ga);
            cp_async16(s0 + POFF_ALO + so, Alo + ga);
            cp_async16(s0 + POFF_BHI + so, Bhi + gb);
            cp_async16(s0 + POFF_BLO + so, Blo + gb);
        }
    };

    const int lr = lane & 7;
    const int lgA_m = ((lane >> 3) & 1) * 8;
    const int lgA_k = (lane >> 4) * 8;
    const int lgB_k = ((lane >> 3) & 1) * 8;

    load_chunk(0, 0);
    CP_COMMIT();

    for (int ch = 0; ch < PNCHUNK; ch++) {
        if (ch + 1 < PNCHUNK) {
            load_chunk((ch + 1) & 1, (ch + 1) * PBK);
            CP_COMMIT();
            CP_WAIT(1);
        } else {
            CP_WAIT(0);
        }
        __syncthreads();

        const uint32_t s0 = sb + (ch & 1) * PSTAGE_B;
        const uint32_t aHi = s0 + POFF_AHI, aLo = s0 + POFF_ALO;
        const uint32_t bHi = s0 + POFF_BHI, bLo = s0 + POFF_BLO;

#pragma unroll
        for (int ks = 0; ks < PBK; ks += 16) {
            uint32_t ahi[4][4], alo[4][4];
#pragma unroll
            for (int mt = 0; mt < 4; mt++) {
                int row = wm * 64 + mt * 16 + lgA_m + lr;
                uint32_t off = (uint32_t)(row * (PPITCH * 2) + (ks + lgA_k) * 2);
                ldsm_x4(ahi[mt], aHi + off);
                ldsm_x4(alo[mt], aLo + off);
            }
#pragma unroll
            for (int nt = 0; nt < 4; nt++) {
                int brow = wn * 32 + nt * 8 + lr;
                uint32_t off = (uint32_t)(brow * (PPITCH * 2) + (ks + lgB_k) * 2);
                uint32_t bh[2], bl[2];
                ldsm_x2(bh, bHi + off);
                ldsm_x2(bl, bLo + off);
#pragma unroll
                for (int mt = 0; mt < 4; mt++) {
                    mma16816(acc[mt][nt], ahi[mt], bh);
                    mma16816(acc[mt][nt], ahi[mt], bl);
                    mma16816(acc[mt][nt], alo[mt], bh);
                }
            }
        }
        __syncthreads();
    }

    // Epilogue: bias add, split to bf16 hi/lo, store
#pragma unroll
    for (int mt = 0; mt < 4; mt++) {
#pragma unroll
        for (int nt = 0; nt < 4; nt++) {
            int row = rowBase + wm * 64 + mt * 16 + (lane >> 2);
            int col = colBase + wn * 32 + nt * 8 + (lane & 3) * 2;
            float2 bb = *(const float2*)&bias[col];
            float v0 = acc[mt][nt][0] + bb.x, v1 = acc[mt][nt][1] + bb.y;
            float v2 = acc[mt][nt][2] + bb.x, v3 = acc[mt][nt][3] + bb.y;
            uint32_t h, l;
            split2(v0, v1, h, l);
            *(uint32_t*)(Chi + (size_t)row * GN + col) = h;
            *(uint32_t*)(Clo + (size_t)row * GN + col) = l;
            split2(v2, v3, h, l);
            *(uint32_t*)(Chi + (size_t)(row + 8) * GN + col) = h;
            *(uint32_t*)(Clo + (size_t)(row + 8) * GN + col) = l;
        }
    }
}

// ---------------------------------------------------------------------------
// Flash attention on mma.sync with compacted keys (R8-verified, unchanged).
// ---------------------------------------------------------------------------
#define AQ 128
#define APITCH 72                       // bf16 elems per smem row (144 B)
#define AT_QH 0
#define AT_QL (AT_QH + AQ * APITCH * 2)             // 18432
#define AT_ST (AT_QL + AQ * APITCH * 2)             // 36864
#define AT_ARR (KT * APITCH * 2)                    // 9216
#define AT_STG (4 * AT_ARR)                         // 36864
#define AT_SMEM (AT_ST + 2 * AT_STG)                // 110592

__global__ __launch_bounds__(256) void attn_mma(float* __restrict__ out) {
    extern __shared__ char smem[];
    const uint32_t sb = smem_u32(smem);

    const int tid = threadIdx.x;
    const int lane = tid & 31;
    const int w = tid >> 5;
    const int q0 = blockIdx.x * AQ;
    const int h = blockIdx.y;
    const int b = blockIdx.z;

    const int nv = g_nv[b];
    const int nt = g_nvt[b];

    const int lr = lane & 7;
    const int lgA_m = ((lane >> 3) & 1) * 8;
    const int lgA_k = (lane >> 4) * 8;
    const int lgB_k = ((lane >> 3) & 1) * 8;
    const int qr = lane >> 2;
    const int qc = (lane & 3) * 2;

    // ---- prologue: q tile + kv tiles 0/1 ----
    const size_t hoff = (size_t)h * DHEAD;
#pragma unroll
    for (int i = 0; i < 8; i++) {
        int seg = tid + i * 256;
        int arr = seg >> 10;
        int s2 = seg & 1023;
        int row = s2 >> 3, c8 = (s2 & 7) * 8;
        const __nv_bfloat16* g = (arr ? g_qlo : g_qhi) +
            (((size_t)b * LQ + q0 + row) * NH) * DHEAD + hoff + c8;
        cp_async16(sb + (arr ? AT_QL : AT_QH) + (uint32_t)((row * APITCH + c8) * 2), g);
    }

    auto load_kv = [&](int stage, int kt) {
        uint32_t s0 = sb + AT_ST + stage * AT_STG;
#pragma unroll
        for (int i = 0; i < 2; i++) {
            int seg = tid + i * 256;
            int row = seg >> 3, c8 = (seg & 7) * 8;
            size_t go = (((size_t)b * LK + kt + row) * NH) * DHEAD + hoff + c8;
            uint32_t so = (uint32_t)((row * APITCH + c8) * 2);
            cp_async16(s0 + 0 * AT_ARR + so, g_khi + go);
            cp_async16(s0 + 1 * AT_ARR + so, g_klo + go);
            cp_async16(s0 + 2 * AT_ARR + so, g_vhi + go);
            cp_async16(s0 + 3 * AT_ARR + so, g_vlo + go);
        }
    };
    load_kv(0, 0);
    CP_COMMIT();
    if (nt > 1) {
        load_kv(1, KT);
        CP_COMMIT();
        CP_WAIT(1);
    } else {
        CP_WAIT(0);
    }
    __syncthreads();

    // ---- q fragments ----
    uint32_t qh[4][4], ql[4][4];
#pragma unroll
    for (int ks = 0; ks < 4; ks++) {
        uint32_t off = (uint32_t)(((w * 16 + lgA_m + lr) * APITCH + ks * 16 + lgA_k) * 2);
        ldsm_x4(qh[ks], sb + AT_QH + off);
        ldsm_x4(ql[ks], sb + AT_QL + off);
    }

    float O[8][4];
#pragma unroll
    for (int d = 0; d < 8; d++) O[d][0] = O[d][1] = O[d][2] = O[d][3] = 0.f;
    float m0 = -INFINITY, m1 = -INFINITY, l0 = 0.f, l1 = 0.f;

    for (int it = 0; it < nt; it++) {
        const uint32_t s0 = sb + AT_ST + (it & 1) * AT_STG;
        const uint32_t kHi = s0, kLo = s0 + AT_ARR;
        const uint32_t vHi = s0 + 2 * AT_ARR, vLo = s0 + 3 * AT_ARR;
        const int ktb = it * KT;

        // ---- S = q . k^T ----
        float S[8][4];
#pragma unroll
        for (int nb = 0; nb < 8; nb++)
            S[nb][0] = S[nb][1] = S[nb][2] = S[nb][3] = 0.f;
#pragma unroll
        for (int ks = 0; ks < 4; ks++) {
#pragma unroll
            for (int nb = 0; nb < 8; nb++) {
                uint32_t off = (uint32_t)(((nb * 8 + lr) * APITCH + ks * 16 + lgB_k) * 2);
                uint32_t kh[2], kl[2];
                ldsm_x2(kh, kHi + off);
                ldsm_x2(kl, kLo + off);
                mma16816(S[nb], qh[ks], kh);
                mma16816(S[nb], qh[ks], kl);
                mma16816(S[nb], ql[ks], kh);
            }
        }

        // ---- scale + tail mask (register compare; exact) ----
#pragma unroll
        for (int nb = 0; nb < 8; nb++) {
            int p0 = ktb + nb * 8 + qc;
            bool v0 = p0 < nv, v1 = p0 + 1 < nv;
            S[nb][0] = v0 ? S[nb][0] * SCALE_L2E : MASKNEG;
            S[nb][1] = v1 ? S[nb][1] * SCALE_L2E : MASKNEG;
            S[nb][2] = v0 ? S[nb][2] * SCALE_L2E : MASKNEG;
            S[nb][3] = v1 ? S[nb][3] * SCALE_L2E : MASKNEG;
        }

        // ---- online softmax ----
        float tm0 = -INFINITY, tm1 = -INFINITY;
#pragma unroll
        for (int nb = 0; nb < 8; nb++) {
            tm0 = fmaxf(tm0, fmaxf(S[nb][0], S[nb][1]));
            tm1 = fmaxf(tm1, fmaxf(S[nb][2], S[nb][3]));
        }
        tm0 = fmaxf(tm0, __shfl_xor_sync(0xffffffffu, tm0, 1));
        tm0 = fmaxf(tm0, __shfl_xor_sync(0xffffffffu, tm0, 2));
        tm1 = fmaxf(tm1, __shfl_xor_sync(0xffffffffu, tm1, 1));
        tm1 = fmaxf(tm1, __shfl_xor_sync(0xffffffffu, tm1, 2));
        float m0n = fmaxf(m0, tm0), m1n = fmaxf(m1, tm1);
        float f0 = exp2f(m0 - m0n), f1 = exp2f(m1 - m1n);
        m0 = m0n;
        m1 = m1n;
#pragma unroll
        for (int d = 0; d < 8; d++) {
            O[d][0] *= f0;
            O[d][1] *= f0;
            O[d][2] *= f1;
            O[d][3] *= f1;
        }
        float rs0 = 0.f, rs1 = 0.f;
#pragma unroll
        for (int nb = 0; nb < 8; nb++) {
            S[nb][0] = exp2f(S[nb][0] - m0);
            S[nb][1] = exp2f(S[nb][1] - m0);
            S[nb][2] = exp2f(S[nb][2] - m1);
            S[nb][3] = exp2f(S[nb][3] - m1);
            rs0 += S[nb][0] + S[nb][1];
            rs1 += S[nb][2] + S[nb][3];
        }
        rs0 += __shfl_xor_sync(0xffffffffu, rs0, 1);
        rs0 += __shfl_xor_sync(0xffffffffu, rs0, 2);
        rs1 += __shfl_xor_sync(0xffffffffu, rs1, 1);
        rs1 += __shfl_xor_sync(0xffffffffu, rs1, 2);
        l0 = l0 * f0 + rs0;
        l1 = l1 * f1 + rs1;

        // ---- pack P hi/lo into A fragments ----
        uint32_t aH[4][4], aL[4][4];
#pragma unroll
        for (int ks2 = 0; ks2 < 4; ks2++) {
            int j0 = 2 * ks2, j1 = 2 * ks2 + 1;
            split2(S[j0][0], S[j0][1], aH[ks2][0], aL[ks2][0]);
            split2(S[j0][2], S[j0][3], aH[ks2][1], aL[ks2][1]);
            split2(S[j1][0], S[j1][1], aH[ks2][2], aL[ks2][2]);
            split2(S[j1][2], S[j1][3], aH[ks2][3], aL[ks2][3]);
        }

        // ---- O += P . V ----
#pragma unroll
        for (int db = 0; db < 8; db++) {
#pragma unroll
            for (int ks2 = 0; ks2 < 4; ks2++) {
                uint32_t off = (uint32_t)(((ks2 * 16 + (lane & 15)) * APITCH + db * 8) * 2);
                uint32_t vh[2], vl[2];
                ldsm_x2t(vh, vHi + off);
                ldsm_x2t(vl, vLo + off);
                mma16816(O[db], aH[ks2], vh);
                mma16816(O[db], aH[ks2], vl);
                mma16816(O[db], aL[ks2], vh);
            }
        }

        __syncthreads();
        if (it + 1 < nt) {
            if (it + 2 < nt) {
                load_kv(it & 1, (it + 2) * KT);
                CP_COMMIT();
                CP_WAIT(1);
            } else {
                CP_WAIT(0);
            }
            __syncthreads();
        }
    }

    // ---- normalize and write ----
    float inv0 = 1.f / l0, inv1 = 1.f / l1;
    int row0 = q0 + w * 16 + qr;
#pragma unroll
    for (int db = 0; db < 8; db++) {
        int col = h * DHEAD + db * 8 + qc;
        float2 o0 = make_float2(O[db][0] * inv0, O[db][1] * inv0);
        float2 o1 = make_float2(O[db][2] * inv1, O[db][3] * inv1);
        *(float2*)&out[((size_t)b * LQ + row0) * GN + col] = o0;
        *(float2*)&out[((size_t)b * LQ + row0 + 8) * GN + col] = o1;
    }
}

// ---------------------------------------------------------------------------
extern "C" void kernel_launch(void* const* d_in, const int* in_sizes, int n_in,
                              void* d_out, int out_size) {
    (void)in_sizes;
    (void)n_in;
    (void)out_size;
    const float* Q = (const float*)d_in[0];
    const float* K = (const float*)d_in[1];
    const float* V = (const float*)d_in[2];
    const int* mask = (const int*)d_in[3];
    const float* Wq = (const float*)d_in[4];
    const float* bq = (const float*)d_in[5];
    const float* Wk = (const float*)d_in[6];
    const float* bk = (const float*)d_in[7];
    const float* Wv = (const float*)d_in[8];
    const float* bv = (const float*)d_in[9];
    float* out = (float*)d_out;

    cudaFuncSetAttribute(proj3, cudaFuncAttributeMaxDynamicSharedMemorySize, PSMEM_B);
    cudaFuncSetAttribute(attn_mma, cudaFuncAttributeMaxDynamicSharedMemorySize, AT_SMEM);

    // 1) mask scan (4 CTAs)
    mask_scan<<<BATCH, 256>>>(mask);

    // 2) all weight transposes (one launch, z = 0..2)
    dim3 tg(GN / 32, GK / 32, 3);
    wtrans3<<<tg, 256>>>(Wq, Wk, Wv);

    // 3) input prep: Q split + K/V gather-split (one launch, z = 0..2)
    dim3 pg(GM * GK / 4 / 256, 1, 3);       // (8192, 1, 3)
    prep3<<<pg, 256>>>(Q, K, V);

    // 4) all three projections (one launch, z = 0..2, wave-packed)
    dim3 gg(GN / PBN, GM / PBM, 3);         // (8, 64, 3)
    proj3<<<gg, 256, PSMEM_B>>>(bq, bk, bv);

    // 5) attention
    dim3 ag(LQ / AQ, NH, BATCH);
    attn_mma<<<ag, 256, AT_SMEM>>>(out);
}

// round 14
// speedup vs baseline: 2.0559x; 1.0070x over previous
#include <cuda_runtime.h>
#include <cuda_bf16.h>
#include <cstdint>
#include <math.h>

// ---------------------------------------------------------------------------
// Problem constants
// ---------------------------------------------------------------------------
#define BATCH 4
#define NH 16
#define LQ 2048
#define LK 2048
#define DHEAD 64

#define GM 8192            // B*LQ
#define GN 1024            // H*DHEAD
#define GK 1024            // D_MODEL

#define SCALE_L2E 0.1803368801111204f   // (1/8) * log2(e)
#define MASKNEG  -1.442695040e9f        // -1e9 * log2(e)

#define KT 64              // attention key tile

// Scratch. q/k/v projected outputs as bf16 hi/lo.
// Q: full rows [b*LQ + q][1024]. K/V: COMPACT rows [b*LK + j][1024] (j < nv128).
__device__ __nv_bfloat16 g_qhi[GM * GN];
__device__ __nv_bfloat16 g_qlo[GM * GN];
__device__ __nv_bfloat16 g_khi[GM * GN];
__device__ __nv_bfloat16 g_klo[GM * GN];
__device__ __nv_bfloat16 g_vhi[GM * GN];
__device__ __nv_bfloat16 g_vlo[GM * GN];
// GEMM A inputs: z=0 (Q split, full), z=1 (K gathered), z=2 (V gathered)
__device__ __nv_bfloat16 g_ahi[GM * GK];
__device__ __nv_bfloat16 g_alo[GM * GK];
__device__ __nv_bfloat16 g_kinh[GM * GK];
__device__ __nv_bfloat16 g_kinl[GM * GK];
__device__ __nv_bfloat16 g_vinh[GM * GK];
__device__ __nv_bfloat16 g_vinl[GM * GK];
// W transposed [z][n][k]
__device__ __nv_bfloat16 g_whi[3 * GN * GK];
__device__ __nv_bfloat16 g_wlo[3 * GN * GK];

// Key compaction state
__device__ int g_idx[BATCH * LK];
__device__ int g_nv[BATCH];     // valid keys
__device__ int g_nvt[BATCH];    // ceil(nv / KT)

// ---------------------------------------------------------------------------
// Helpers (baseline PTX: ldmatrix / mma.sync / cp.async)
// ---------------------------------------------------------------------------
__device__ __forceinline__ uint32_t smem_u32(const void* p) {
    uint32_t a;
    asm("{ .reg .u64 t; cvta.to.shared.u64 t, %1; cvt.u32.u64 %0, t; }"
        : "=r"(a) : "l"(p));
    return a;
}
__device__ __forceinline__ void cp_async16(uint32_t s, const void* g) {
    asm volatile("cp.async.cg.shared.global [%0], [%1], 16;" :: "r"(s), "l"(g));
}
#define CP_COMMIT() asm volatile("cp.async.commit_group;")
#define CP_WAIT(n) asm volatile("cp.async.wait_group %0;" :: "n"(n))

__device__ __forceinline__ void ldsm_x4(uint32_t* r, uint32_t addr) {
    asm volatile("ldmatrix.sync.aligned.m8n8.x4.shared.b16 {%0,%1,%2,%3}, [%4];"
                 : "=r"(r[0]), "=r"(r[1]), "=r"(r[2]), "=r"(r[3]) : "r"(addr));
}
__device__ __forceinline__ void ldsm_x2(uint32_t* r, uint32_t addr) {
    asm volatile("ldmatrix.sync.aligned.m8n8.x2.shared.b16 {%0,%1}, [%2];"
                 : "=r"(r[0]), "=r"(r[1]) : "r"(addr));
}
__device__ __forceinline__ void ldsm_x2t(uint32_t* r, uint32_t addr) {
    asm volatile("ldmatrix.sync.aligned.m8n8.x2.trans.shared.b16 {%0,%1}, [%2];"
                 : "=r"(r[0]), "=r"(r[1]) : "r"(addr));
}
__device__ __forceinline__ void mma16816(float* c, const uint32_t* a, const uint32_t* b) {
    asm volatile(
        "mma.sync.aligned.m16n8k16.row.col.f32.bf16.bf16.f32 "
        "{%0,%1,%2,%3}, {%4,%5,%6,%7}, {%8,%9}, {%0,%1,%2,%3};"
        : "+f"(c[0]), "+f"(c[1]), "+f"(c[2]), "+f"(c[3])
        : "r"(a[0]), "r"(a[1]), "r"(a[2]), "r"(a[3]), "r"(b[0]), "r"(b[1]));
}

// (x,y) -> packed bf16x2 hi and lo residual
__device__ __forceinline__ void split2(float x, float y, uint32_t& h, uint32_t& l) {
    __nv_bfloat162 hh = __floats2bfloat162_rn(x, y);
    float hx = __bfloat162float(hh.x), hy = __bfloat162float(hh.y);
    __nv_bfloat162 ll = __floats2bfloat162_rn(x - hx, y - hy);
    h = *(uint32_t*)&hh;
    l = *(uint32_t*)&ll;
}
__device__ __forceinline__ uint32_t pack2(float a, float b) {
    __nv_bfloat162 t = __floats2bfloat162_rn(a, b);
    return *(uint32_t*)&t;
}

// ---------------------------------------------------------------------------
// Mask scan: per-batch valid-key index list (block-wide scan, 1 CTA/batch)
// ---------------------------------------------------------------------------
__global__ __launch_bounds__(256) void mask_scan(const int* __restrict__ mask) {
    __shared__ int wsum[8];
    const int b = blockIdx.x;
    const int* m = mask + b * LK;
    const int tid = threadIdx.x;
    const int lane = tid & 31, w = tid >> 5;

    int v[8], s = 0;
#pragma unroll
    for (int i = 0; i < 8; i++) {
        v[i] = (m[tid * 8 + i] != 0);
        s += v[i];
    }
    int ps = s;
#pragma unroll
    for (int o = 1; o < 32; o <<= 1) {
        int t = __shfl_up_sync(0xffffffffu, ps, o);
        if (lane >= o) ps += t;
    }
    if (lane == 31) wsum[w] = ps;
    __syncthreads();
    if (w == 0) {
        int t = (lane < 8) ? wsum[lane] : 0;
#pragma unroll
        for (int o = 1; o < 8; o <<= 1) {
            int u = __shfl_up_sync(0xffffffffu, t, o);
            if (lane >= o) t += u;
        }
        if (lane < 8) wsum[lane] = t;
    }
    __syncthreads();
    int excl = ps - s + (w ? wsum[w - 1] : 0);
#pragma unroll
    for (int i = 0; i < 8; i++) {
        if (v[i]) g_idx[b * LK + excl++] = tid * 8 + i;
    }
    if (tid == 255) {
        int nv = wsum[7];
        g_nv[b] = nv;
        g_nvt[b] = (nv + KT - 1) / KT;
    }
}

// ---------------------------------------------------------------------------
// wtrans3: W[z] [k][n] fp32 -> g_whi/g_wlo[z] bf16 [n][k]. z = blockIdx.z.
// ---------------------------------------------------------------------------
__global__ __launch_bounds__(256) void wtrans3(const float* __restrict__ W0,
                                               const float* __restrict__ W1,
                                               const float* __restrict__ W2) {
    __shared__ float t[32][33];
    const int z = blockIdx.z;
    const float* W = (z == 0) ? W0 : (z == 1) ? W1 : W2;
    __nv_bfloat16* thi = g_whi + (size_t)z * GN * GK;
    __nv_bfloat16* tlo = g_wlo + (size_t)z * GN * GK;

    int n0 = blockIdx.x * 32, k0 = blockIdx.y * 32;
    int tx = threadIdx.x & 31, ty0 = threadIdx.x >> 5;
#pragma unroll
    for (int i = 0; i < 4; i++) {
        int ty = ty0 + i * 8;
        t[ty][tx] = W[(size_t)(k0 + ty) * GN + n0 + tx];
    }
    __syncthreads();
#pragma unroll
    for (int i = 0; i < 4; i++) {
        int ty = ty0 + i * 8;
        float v = t[tx][ty];
        __nv_bfloat16 h = __float2bfloat16(v);
        size_t o = (size_t)(n0 + ty) * GK + k0 + tx;
        thi[o] = h;
        tlo[o] = __float2bfloat16(v - __bfloat162float(h));
    }
}

// ---------------------------------------------------------------------------
// prep3: z=0 split Q (full); z=1 gather+split K; z=2 gather+split V.
// ---------------------------------------------------------------------------
__global__ __launch_bounds__(256) void prep3(const float* __restrict__ Q,
                                             const float* __restrict__ K,
                                             const float* __restrict__ V) {
    const int z = blockIdx.z;
    const int tid = threadIdx.x;

    if (z == 0) {
        int i = blockIdx.x * 256 + tid;
        float4 v = ((const float4*)Q)[i];
        float h0 = __bfloat162float(__float2bfloat16(v.x));
        float h1 = __bfloat162float(__float2bfloat16(v.y));
        float h2 = __bfloat162float(__float2bfloat16(v.z));
        float h3 = __bfloat162float(__float2bfloat16(v.w));
        uint2 H, L;
        H.x = pack2(h0, h1);
        H.y = pack2(h2, h3);
        L.x = pack2(v.x - h0, v.y - h1);
        L.y = pack2(v.z - h2, v.w - h3);
        ((uint2*)g_ahi)[i] = H;
        ((uint2*)g_alo)[i] = L;
        return;
    }

    const int x = blockIdx.x;
    if (x >= 256 * BATCH) return;
    const int b = x >> 8;
    const int j0 = (x & 255) * 8;
    const int nv = g_nv[b];
    const int nv128 = (nv + 127) & ~127;
    if (j0 >= nv128) return;

    const float* X = (z == 1) ? K : V;
    __nv_bfloat16* dh = (z == 1) ? g_kinh : g_vinh;
    __nv_bfloat16* dl = (z == 1) ? g_kinl : g_vinl;

#pragma unroll
    for (int i = 0; i < 8; i++) {
        int j = j0 + i;
        if (j >= nv128) break;
        uint2 H = make_uint2(0, 0), L = make_uint2(0, 0);
        if (j < nv) {
            int s = g_idx[b * LK + j];
            float4 v = *(const float4*)(X + ((size_t)b * LK + s) * GK + tid * 4);
            float h0 = __bfloat162float(__float2bfloat16(v.x));
            float h1 = __bfloat162float(__float2bfloat16(v.y));
            float h2 = __bfloat162float(__float2bfloat16(v.z));
            float h3 = __bfloat162float(__float2bfloat16(v.w));
            H.x = pack2(h0, h1);
            H.y = pack2(h2, h3);
            L.x = pack2(v.x - h0, v.y - h1);
            L.y = pack2(v.z - h2, v.w - h3);
        }
        size_t o = ((size_t)b * LK + j) * GK + tid * 4;
        *(uint2*)(dh + o) = H;
        *(uint2*)(dl + o) = L;
    }
}

// ---------------------------------------------------------------------------
// proj3: fused projection GEMMs, 2 CTAs/SM.
// Term-major MMA issue: dependent-chain distance 4 (vs 1 before).
// ---------------------------------------------------------------------------
#define PBM 128
#define PBN 128
#define PBK 32
#define PPITCH 40
#define PTILE_B (128 * PPITCH * 2)
#define POFF_AHI 0
#define POFF_ALO (POFF_AHI + PTILE_B)
#define POFF_BHI (POFF_ALO + PTILE_B)
#define POFF_BLO (POFF_BHI + PTILE_B)
#define PSTAGE_B (4 * PTILE_B)
#define PSMEM_B (2 * PSTAGE_B)
#define PNCHUNK (GK / PBK)

__global__ __launch_bounds__(256, 2) void proj3(const float* __restrict__ bq,
                                                const float* __restrict__ bk,
                                                const float* __restrict__ bv) {
    const int z = blockIdx.z;
    const int rowBase = blockIdx.y * PBM;
    if (z > 0) {
        int b = rowBase / LQ;
        int nv128 = (g_nv[b] + 127) & ~127;
        if ((rowBase % LQ) >= nv128) return;
    }

    const __nv_bfloat16* Ahi = (z == 0) ? g_ahi : (z == 1) ? g_kinh : g_vinh;
    const __nv_bfloat16* Alo = (z == 0) ? g_alo : (z == 1) ? g_kinl : g_vinl;
    const __nv_bfloat16* Bhi = g_whi + (size_t)z * GN * GK;
    const __nv_bfloat16* Blo = g_wlo + (size_t)z * GN * GK;
    const float* bias = (z == 0) ? bq : (z == 1) ? bk : bv;
    __nv_bfloat16* Chi = (z == 0) ? g_qhi : (z == 1) ? g_khi : g_vhi;
    __nv_bfloat16* Clo = (z == 0) ? g_qlo : (z == 1) ? g_klo : g_vlo;

    extern __shared__ char smem[];
    const uint32_t sb = smem_u32(smem);
    const int tid = threadIdx.x;
    const int lane = tid & 31;
    const int warp = tid >> 5;
    const int wm = warp & 1;
    const int wn = warp >> 1;
    const int colBase = blockIdx.x * PBN;

    float acc[4][4][4];
#pragma unroll
    for (int i = 0; i < 4; i++)
#pragma unroll
        for (int j = 0; j < 4; j++)
#pragma unroll
            for (int r = 0; r < 4; r++) acc[i][j][r] = 0.f;

    auto load_chunk = [&](int stage, int kb) {
        uint32_t s0 = sb + stage * PSTAGE_B;
#pragma unroll
        for (int i = 0; i < 2; i++) {
            int c = tid + i * 256;
            int r = c >> 2;
            int col = (c & 3) * 8;
            uint32_t so = (uint32_t)(r * (PPITCH * 2) + col * 2);
            size_t ga = (size_t)(rowBase + r) * GK + kb + col;
            size_t gb = (size_t)(colBase + r) * GK + kb + col;
            cp_async16(s0 + POFF_AHI + so, Ahi + ga);
            cp_async16(s0 + POFF_ALO + so, Alo + ga);
            cp_async16(s0 + POFF_BHI + so, Bhi + gb);
            cp_async16(s0 + POFF_BLO + so, Blo + gb);
        }
    };

    const int lr = lane & 7;
    const int lgA_m = ((lane >> 3) & 1) * 8;
    const int lgA_k = (lane >> 4) * 8;
    const int lgB_k = ((lane >> 3) & 1) * 8;

    load_chunk(0, 0);
    CP_COMMIT();

    for (int ch = 0; ch < PNCHUNK; ch++) {
        if (ch + 1 < PNCHUNK) {
            load_chunk((ch + 1) & 1, (ch + 1) * PBK);
            CP_COMMIT();
            CP_WAIT(1);
        } else {
            CP_WAIT(0);
        }
        __syncthreads();

        const uint32_t s0 = sb + (ch & 1) * PSTAGE_B;
        const uint32_t aHi = s0 + POFF_AHI, aLo = s0 + POFF_ALO;
        const uint32_t bHi = s0 + POFF_BHI, bLo = s0 + POFF_BLO;

#pragma unroll
        for (int ks = 0; ks < PBK; ks += 16) {
            uint32_t ahi[4][4], alo[4][4];
#pragma unroll
            for (int mt = 0; mt < 4; mt++) {
                int row = wm * 64 + mt * 16 + lgA_m + lr;
                uint32_t off = (uint32_t)(row * (PPITCH * 2) + (ks + lgA_k) * 2);
                ldsm_x4(ahi[mt], aHi + off);
                ldsm_x4(alo[mt], aLo + off);
            }
#pragma unroll
            for (int nt = 0; nt < 4; nt++) {
                int brow = wn * 32 + nt * 8 + lr;
                uint32_t off = (uint32_t)(brow * (PPITCH * 2) + (ks + lgB_k) * 2);
                uint32_t bh[2], bl[2];
                ldsm_x2(bh, bHi + off);
                ldsm_x2(bl, bLo + off);
                // term-major: 4 independent chains between dependent MMAs
#pragma unroll
                for (int mt = 0; mt < 4; mt++) mma16816(acc[mt][nt], ahi[mt], bh);
#pragma unroll
                for (int mt = 0; mt < 4; mt++) mma16816(acc[mt][nt], ahi[mt], bl);
#pragma unroll
                for (int mt = 0; mt < 4; mt++) mma16816(acc[mt][nt], alo[mt], bh);
            }
        }
        __syncthreads();
    }

    // Epilogue: bias add, split to bf16 hi/lo, store
#pragma unroll
    for (int mt = 0; mt < 4; mt++) {
#pragma unroll
        for (int nt = 0; nt < 4; nt++) {
            int row = rowBase + wm * 64 + mt * 16 + (lane >> 2);
            int col = colBase + wn * 32 + nt * 8 + (lane & 3) * 2;
            float2 bb = *(const float2*)&bias[col];
            float v0 = acc[mt][nt][0] + bb.x, v1 = acc[mt][nt][1] + bb.y;
            float v2 = acc[mt][nt][2] + bb.x, v3 = acc[mt][nt][3] + bb.y;
            uint32_t h, l;
            split2(v0, v1, h, l);
            *(uint32_t*)(Chi + (size_t)row * GN + col) = h;
            *(uint32_t*)(Clo + (size_t)row * GN + col) = l;
            split2(v2, v3, h, l);
            *(uint32_t*)(Chi + (size_t)(row + 8) * GN + col) = h;
            *(uint32_t*)(Clo + (size_t)(row + 8) * GN + col) = l;
        }
    }
}

// ---------------------------------------------------------------------------
// Flash attention on mma.sync with compacted keys.
// R8 structure; MMA issue reordered into paired interleaved chains.
// ---------------------------------------------------------------------------
#define AQ 128
#define APITCH 72                       // bf16 elems per smem row (144 B)
#define AT_QH 0
#define AT_QL (AT_QH + AQ * APITCH * 2)             // 18432
#define AT_ST (AT_QL + AQ * APITCH * 2)             // 36864
#define AT_ARR (KT * APITCH * 2)                    // 9216
#define AT_STG (4 * AT_ARR)                         // 36864
#define AT_SMEM (AT_ST + 2 * AT_STG)                // 110592

__global__ __launch_bounds__(256) void attn_mma(float* __restrict__ out) {
    extern __shared__ char smem[];
    const uint32_t sb = smem_u32(smem);

    const int tid = threadIdx.x;
    const int lane = tid & 31;
    const int w = tid >> 5;
    const int q0 = blockIdx.x * AQ;
    const int h = blockIdx.y;
    const int b = blockIdx.z;

    const int nv = g_nv[b];
    const int nt = g_nvt[b];

    const int lr = lane & 7;
    const int lgA_m = ((lane >> 3) & 1) * 8;
    const int lgA_k = (lane >> 4) * 8;
    const int lgB_k = ((lane >> 3) & 1) * 8;
    const int qr = lane >> 2;
    const int qc = (lane & 3) * 2;

    // ---- prologue: q tile + kv tiles 0/1 ----
    const size_t hoff = (size_t)h * DHEAD;
#pragma unroll
    for (int i = 0; i < 8; i++) {
        int seg = tid + i * 256;
        int arr = seg >> 10;
        int s2 = seg & 1023;
        int row = s2 >> 3, c8 = (s2 & 7) * 8;
        const __nv_bfloat16* g = (arr ? g_qlo : g_qhi) +
            (((size_t)b * LQ + q0 + row) * NH) * DHEAD + hoff + c8;
        cp_async16(sb + (arr ? AT_QL : AT_QH) + (uint32_t)((row * APITCH + c8) * 2), g);
    }

    auto load_kv = [&](int stage, int kt) {
        uint32_t s0 = sb + AT_ST + stage * AT_STG;
#pragma unroll
        for (int i = 0; i < 2; i++) {
            int seg = tid + i * 256;
            int row = seg >> 3, c8 = (seg & 7) * 8;
            size_t go = (((size_t)b * LK + kt + row) * NH) * DHEAD + hoff + c8;
            uint32_t so = (uint32_t)((row * APITCH + c8) * 2);
            cp_async16(s0 + 0 * AT_ARR + so, g_khi + go);
            cp_async16(s0 + 1 * AT_ARR + so, g_klo + go);
            cp_async16(s0 + 2 * AT_ARR + so, g_vhi + go);
            cp_async16(s0 + 3 * AT_ARR + so, g_vlo + go);
        }
    };
    load_kv(0, 0);
    CP_COMMIT();
    if (nt > 1) {
        load_kv(1, KT);
        CP_COMMIT();
        CP_WAIT(1);
    } else {
        CP_WAIT(0);
    }
    __syncthreads();

    // ---- q fragments ----
    uint32_t qh[4][4], ql[4][4];
#pragma unroll
    for (int ks = 0; ks < 4; ks++) {
        uint32_t off = (uint32_t)(((w * 16 + lgA_m + lr) * APITCH + ks * 16 + lgA_k) * 2);
        ldsm_x4(qh[ks], sb + AT_QH + off);
        ldsm_x4(ql[ks], sb + AT_QL + off);
    }

    float O[8][4];
#pragma unroll
    for (int d = 0; d < 8; d++) O[d][0] = O[d][1] = O[d][2] = O[d][3] = 0.f;
    float m0 = -INFINITY, m1 = -INFINITY, l0 = 0.f, l1 = 0.f;

    for (int it = 0; it < nt; it++) {
        const uint32_t s0 = sb + AT_ST + (it & 1) * AT_STG;
        const uint32_t kHi = s0, kLo = s0 + AT_ARR;
        const uint32_t vHi = s0 + 2 * AT_ARR, vLo = s0 + 3 * AT_ARR;
        const int ktb = it * KT;

        // ---- S = q . k^T (paired n-blocks, interleaved chains) ----
        float S[8][4];
#pragma unroll
        for (int nb = 0; nb < 8; nb++)
            S[nb][0] = S[nb][1] = S[nb][2] = S[nb][3] = 0.f;
#pragma unroll
        for (int ks = 0; ks < 4; ks++) {
#pragma unroll
            for (int nbp = 0; nbp < 4; nbp++) {
                const int nb0 = 2 * nbp, nb1 = nb0 + 1;
                uint32_t off0 = (uint32_t)(((nb0 * 8 + lr) * APITCH + ks * 16 + lgB_k) * 2);
                uint32_t off1 = (uint32_t)(((nb1 * 8 + lr) * APITCH + ks * 16 + lgB_k) * 2);
                uint32_t kh0[2], kl0[2], kh1[2], kl1[2];
                ldsm_x2(kh0, kHi + off0);
                ldsm_x2(kl0, kLo + off0);
                ldsm_x2(kh1, kHi + off1);
                ldsm_x2(kl1, kLo + off1);
                mma16816(S[nb0], qh[ks], kh0);
                mma16816(S[nb1], qh[ks], kh1);
                mma16816(S[nb0], qh[ks], kl0);
                mma16816(S[nb1], qh[ks], kl1);
                mma16816(S[nb0], ql[ks], kh0);
                mma16816(S[nb1], ql[ks], kh1);
            }
        }

        // ---- scale + tail mask (register compare; exact) ----
#pragma unroll
        for (int nb = 0; nb < 8; nb++) {
            int p0 = ktb + nb * 8 + qc;
            bool v0 = p0 < nv, v1 = p0 + 1 < nv;
            S[nb][0] = v0 ? S[nb][0] * SCALE_L2E : MASKNEG;
            S[nb][1] = v1 ? S[nb][1] * SCALE_L2E : MASKNEG;
            S[nb][2] = v0 ? S[nb][2] * SCALE_L2E : MASKNEG;
            S[nb][3] = v1 ? S[nb][3] * SCALE_L2E : MASKNEG;
        }

        // ---- online softmax ----
        float tm0 = -INFINITY, tm1 = -INFINITY;
#pragma unroll
        for (int nb = 0; nb < 8; nb++) {
            tm0 = fmaxf(tm0, fmaxf(S[nb][0], S[nb][1]));
            tm1 = fmaxf(tm1, fmaxf(S[nb][2], S[nb][3]));
        }
        tm0 = fmaxf(tm0, __shfl_xor_sync(0xffffffffu, tm0, 1));
        tm0 = fmaxf(tm0, __shfl_xor_sync(0xffffffffu, tm0, 2));
        tm1 = fmaxf(tm1, __shfl_xor_sync(0xffffffffu, tm1, 1));
        tm1 = fmaxf(tm1, __shfl_xor_sync(0xffffffffu, tm1, 2));
        float m0n = fmaxf(m0, tm0), m1n = fmaxf(m1, tm1);
        float f0 = exp2f(m0 - m0n), f1 = exp2f(m1 - m1n);
        m0 = m0n;
        m1 = m1n;
#pragma unroll
        for (int d = 0; d < 8; d++) {
            O[d][0] *= f0;
            O[d][1] *= f0;
            O[d][2] *= f1;
            O[d][3] *= f1;
        }
        float rs0 = 0.f, rs1 = 0.f;
#pragma unroll
        for (int nb = 0; nb < 8; nb++) {
            S[nb][0] = exp2f(S[nb][0] - m0);
            S[nb][1] = exp2f(S[nb][1] - m0);
            S[nb][2] = exp2f(S[nb][2] - m1);
            S[nb][3] = exp2f(S[nb][3] - m1);
            rs0 += S[nb][0] + S[nb][1];
            rs1 += S[nb][2] + S[nb][3];
        }
        rs0 += __shfl_xor_sync(0xffffffffu, rs0, 1);
        rs0 += __shfl_xor_sync(0xffffffffu, rs0, 2);
        rs1 += __shfl_xor_sync(0xffffffffu, rs1, 1);
        rs1 += __shfl_xor_sync(0xffffffffu, rs1, 2);
        l0 = l0 * f0 + rs0;
        l1 = l1 * f1 + rs1;

        // ---- pack P hi/lo into A fragments ----
        uint32_t aH[4][4], aL[4][4];
#pragma unroll
        for (int ks2 = 0; ks2 < 4; ks2++) {
            int j0 = 2 * ks2, j1 = 2 * ks2 + 1;
            split2(S[j0][0], S[j0][1], aH[ks2][0], aL[ks2][0]);
            split2(S[j0][2], S[j0][3], aH[ks2][1], aL[ks2][1]);
            split2(S[j1][0], S[j1][1], aH[ks2][2], aL[ks2][2]);
            split2(S[j1][2], S[j1][3], aH[ks2][3], aL[ks2][3]);
        }

        // ---- O += P . V (paired d-blocks, interleaved chains) ----
#pragma unroll
        for (int dbp = 0; dbp < 4; dbp++) {
            const int db0 = 2 * dbp, db1 = db0 + 1;
#pragma unroll
            for (int ks2 = 0; ks2 < 4; ks2++) {
                uint32_t off0 =
                    (uint32_t)(((ks2 * 16 + (lane & 15)) * APITCH + db0 * 8) * 2);
                uint32_t off1 =
                    (uint32_t)(((ks2 * 16 + (lane & 15)) * APITCH + db1 * 8) * 2);
                uint32_t vh0[2], vl0[2], vh1[2], vl1[2];
                ldsm_x2t(vh0, vHi + off0);
                ldsm_x2t(vl0, vLo + off0);
                ldsm_x2t(vh1, vHi + off1);
                ldsm_x2t(vl1, vLo + off1);
                mma16816(O[db0], aH[ks2], vh0);
                mma16816(O[db1], aH[ks2], vh1);
                mma16816(O[db0], aH[ks2], vl0);
                mma16816(O[db1], aH[ks2], vl1);
                mma16816(O[db0], aL[ks2], vh0);
                mma16816(O[db1], aL[ks2], vh1);
            }
        }

        __syncthreads();
        if (it + 1 < nt) {
            if (it + 2 < nt) {
                load_kv(it & 1, (it + 2) * KT);
                CP_COMMIT();
                CP_WAIT(1);
            } else {
                CP_WAIT(0);
            }
            __syncthreads();
        }
    }

    // ---- normalize and write ----
    float inv0 = 1.f / l0, inv1 = 1.f / l1;
    int row0 = q0 + w * 16 + qr;
#pragma unroll
    for (int db = 0; db < 8; db++) {
        int col = h * DHEAD + db * 8 + qc;
        float2 o0 = make_float2(O[db][0] * inv0, O[db][1] * inv0);
        float2 o1 = make_float2(O[db][2] * inv1, O[db][3] * inv1);
        *(float2*)&out[((size_t)b * LQ + row0) * GN + col] = o0;
        *(float2*)&out[((size_t)b * LQ + row0 + 8) * GN + col] = o1;
    }
}

// ---------------------------------------------------------------------------
extern "C" void kernel_launch(void* const* d_in, const int* in_sizes, int n_in,
                              void* d_out, int out_size) {
    (void)in_sizes;
    (void)n_in;
    (void)out_size;
    const float* Q = (const float*)d_in[0];
    const float* K = (const float*)d_in[1];
    const float* V = (const float*)d_in[2];
    const int* mask = (const int*)d_in[3];
    const float* Wq = (const float*)d_in[4];
    const float* bq = (const float*)d_in[5];
    const float* Wk = (const float*)d_in[6];
    const float* bk = (const float*)d_in[7];
    const float* Wv = (const float*)d_in[8];
    const float* bv = (const float*)d_in[9];
    float* out = (float*)d_out;

    cudaFuncSetAttribute(proj3, cudaFuncAttributeMaxDynamicSharedMemorySize, PSMEM_B);
    cudaFuncSetAttribute(attn_mma, cudaFuncAttributeMaxDynamicSharedMemorySize, AT_SMEM);

    mask_scan<<<BATCH, 256>>>(mask);

    dim3 tg(GN / 32, GK / 32, 3);
    wtrans3<<<tg, 256>>>(Wq, Wk, Wv);

    dim3 pg(GM * GK / 4 / 256, 1, 3);
    prep3<<<pg, 256>>>(Q, K, V);

    dim3 gg(GN / PBN, GM / PBM, 3);
    proj3<<<gg, 256, PSMEM_B>>>(bq, bk, bv);

    dim3 ag(LQ / AQ, NH, BATCH);
    attn_mma<<<ag, 256, AT_SMEM>>>(out);
}